// round 14
// baseline (speedup 1.0000x reference)
#include <cuda_runtime.h>
#include <cuda_bf16.h>
#include <math.h>
#include <stdint.h>

#define NBATCH 4
#define SEQ    1024
#define EMBED  2048
#define EBS    512
#define NB     4
#define HEADS  8
#define HD     64
#define TTOK   (NBATCH * SEQ)        /* 4096 tokens */
#define NG     (NBATCH * NB * HEADS) /* 128 (n,b,h) heads */

typedef unsigned long long u64;

#define SMEM_SWIZZLE_128B(off) ((off) ^ (((off) >> 3) & 0x70))

/* ================================================================== */
/* Tensor / async helpers (sm_80 path: legal on base sm_103 target)    */
/* ================================================================== */
__device__ __forceinline__ uint32_t smem_to_u32(const void* p) {
    uint32_t a;
    asm("{ .reg .u64 t; cvta.to.shared.u64 t, %1; cvt.u32.u64 %0, t; }"
        : "=r"(a) : "l"(p));
    return a;
}
__device__ __forceinline__ void ldsm4(uint32_t* r, uint32_t addr) {
    asm volatile("ldmatrix.sync.aligned.m8n8.x4.shared.b16 {%0,%1,%2,%3}, [%4];"
                 : "=r"(r[0]), "=r"(r[1]), "=r"(r[2]), "=r"(r[3]) : "r"(addr));
}
__device__ __forceinline__ void mma16816(float* d, const uint32_t* a,
                                         const uint32_t* b) {
    asm volatile(
        "mma.sync.aligned.m16n8k16.row.col.f32.bf16.bf16.f32 "
        "{%0,%1,%2,%3}, {%4,%5,%6,%7}, {%8,%9}, {%0,%1,%2,%3};"
        : "+f"(d[0]), "+f"(d[1]), "+f"(d[2]), "+f"(d[3])
        : "r"(a[0]), "r"(a[1]), "r"(a[2]), "r"(a[3]), "r"(b[0]), "r"(b[1]));
}
__device__ __forceinline__ void cpa16(uint32_t dst, const void* src) {
    asm volatile("cp.async.cg.shared.global [%0], [%1], 16;"
                 :: "r"(dst), "l"(src) : "memory");
}
#define CP_COMMIT() asm volatile("cp.async.commit_group;" ::: "memory")
#define CP_WAIT1()  asm volatile("cp.async.wait_group 1;" ::: "memory")
#define CP_WAIT0()  asm volatile("cp.async.wait_group 0;" ::: "memory")
__device__ __forceinline__ uint32_t packbf2(float a, float b) {
    __nv_bfloat162 p = __floats2bfloat162_rn(a, b);
    return *(uint32_t*)&p;
}
__device__ __forceinline__ void splitf(float v, float& hi, float& lo) {
    __nv_bfloat16 hb = __float2bfloat16_rn(v);
    hi = __bfloat162float(hb);
    lo = v - hi;
}
__device__ __forceinline__ float2 upk(uint32_t u) {
    __nv_bfloat162 b = *(__nv_bfloat162*)&u;
    return __bfloat1622float2(b);
}

/* ================================================================== */
/* Device scratch                                                      */
/* ================================================================== */
__device__ __align__(256) __nv_bfloat16 g_Eh[(size_t)NG * SEQ * SEQ]; /* 256 MB */
__device__ __align__(256) __nv_bfloat16 g_El[(size_t)NG * SEQ * SEQ]; /* 256 MB */
__device__ __align__(256) float g_Zp[16][NG * SEQ];
__device__ float g_Zi[NG * SEQ];
__device__ __align__(256) uint32_t g_Mb[NBATCH * SEQ * 32];           /* bit mask */
__device__ __align__(256) __nv_bfloat16 g_Xh[(size_t)3 * TTOK * EMBED];
__device__ __align__(256) __nv_bfloat16 g_Xl[(size_t)3 * TTOK * EMBED];
__device__ __align__(256) __nv_bfloat16 g_AOh[(size_t)TTOK * EMBED];
__device__ __align__(256) __nv_bfloat16 g_AOl[(size_t)TTOK * EMBED];
__device__ __align__(256) __nv_bfloat16 g_Wh[(size_t)4 * NB * EBS * EBS];
__device__ __align__(256) __nv_bfloat16 g_Wl[(size_t)4 * NB * EBS * EBS];
__device__ __align__(256) __nv_bfloat16 g_Qh[(size_t)NG * SEQ * HD];
__device__ __align__(256) __nv_bfloat16 g_Ql[(size_t)NG * SEQ * HD];
__device__ __align__(256) __nv_bfloat16 g_Kh[(size_t)NG * SEQ * HD];
__device__ __align__(256) __nv_bfloat16 g_Kl[(size_t)NG * SEQ * HD];
__device__ __align__(256) __nv_bfloat16 g_Vth[(size_t)NG * HD * SEQ]; /* [g][d][s] */
__device__ __align__(256) __nv_bfloat16 g_Vtl[(size_t)NG * HD * SEQ];

/* ================================================================== */
/* Converters                                                          */
/* ================================================================== */
__global__ __launch_bounds__(256) void convx_kernel(
    const float* __restrict__ V, const float* __restrict__ K,
    const float* __restrict__ Q)
{
    const int p = blockIdx.y;
    const float* src = (p == 0) ? V : (p == 1) ? K : Q;
    __nv_bfloat16* dh = g_Xh + (size_t)p * TTOK * EMBED;
    __nv_bfloat16* dl = g_Xl + (size_t)p * TTOK * EMBED;
    const size_t i = ((size_t)blockIdx.x * 256 + threadIdx.x) * 4;
    float4 v = *(const float4*)(src + i);
    float f[4] = {v.x, v.y, v.z, v.w};
    float hi[4], lo[4];
#pragma unroll
    for (int j = 0; j < 4; j++) splitf(f[j], hi[j], lo[j]);
    uint2 hv, lv;
    hv.x = packbf2(hi[0], hi[1]); hv.y = packbf2(hi[2], hi[3]);
    lv.x = packbf2(lo[0], lo[1]); lv.y = packbf2(lo[2], lo[3]);
    *(uint2*)(dh + i) = hv;
    *(uint2*)(dl + i) = lv;
}

__global__ __launch_bounds__(256) void convw_kernel(
    const float* __restrict__ Wv, const float* __restrict__ Wk,
    const float* __restrict__ Wq, const float* __restrict__ Wo)
{
    __shared__ float st[32][33];
    const int z = blockIdx.z;
    const int wi = z >> 2, b = z & 3;
    const float* W = ((wi == 0) ? Wv : (wi == 1) ? Wk : (wi == 2) ? Wq : Wo)
                     + (size_t)b * EBS * EBS;
    const int i0 = blockIdx.y * 32, o0 = blockIdx.x * 32;
    const int tx = threadIdx.x, ty = threadIdx.y;
#pragma unroll
    for (int kk = 0; kk < 4; kk++)
        st[ty + 8 * kk][tx] = W[(size_t)(i0 + ty + 8 * kk) * EBS + o0 + tx];
    __syncthreads();
    __nv_bfloat16* oh = g_Wh + (size_t)(wi * NB + b) * EBS * EBS;
    __nv_bfloat16* ol = g_Wl + (size_t)(wi * NB + b) * EBS * EBS;
#pragma unroll
    for (int kk = 0; kk < 4; kk++) {
        const float v = st[tx][ty + 8 * kk];
        float h, l;
        splitf(v, h, l);
        const size_t off = (size_t)(o0 + ty + 8 * kk) * EBS + i0 + tx;
        oh[off] = __float2bfloat16_rn(h);
        ol[off] = __float2bfloat16_rn(l);
    }
}

/* pack mask int32 -> bits */
__global__ __launch_bounds__(256) void convm_kernel(const int* __restrict__ mask)
{
    const int wid = threadIdx.x >> 5, lane = threadIdx.x & 31;
    const int r = blockIdx.x * 8 + wid;
    const int* row = mask + (size_t)r * SEQ;
    uint32_t* orow = g_Mb + (size_t)r * 32;
    for (int w = 0; w < 32; w++) {
        const int m = row[w * 32 + lane];
        const uint32_t bits = __ballot_sync(0xffffffffu, m != 0);
        if (lane == 0) orow[w] = bits;
    }
}

/* ================================================================== */
/* mma.sync bf16 3-split projection GEMM.                              */
/* 512 threads, 16 warps as 4m x 4n, warp tile 64x32 -> CTA 256x128.   */
/* K=512 in 8 chunks of 64; double-buffered cp.async (2 x 96 KB).      */
/* ================================================================== */
#define KCHUNK 64
#define NCHUNKS 8
#define A_TILE 32768                      /* 256 x 128B */
#define B_TILE 16384                      /* 128 x 128B */
#define MMBUF (2 * A_TILE + 2 * B_TILE)   /* 96 KB per chunk buffer */
#define SS 132
#define SMEM_GEMM_TOTAL (2 * MMBUF)       /* 192 KB */

template <int MODE>
__global__ __launch_bounds__(512) void mm_kernel(
    const float* __restrict__ bias0, const float* __restrict__ bias1,
    const float* __restrict__ bias2, float* __restrict__ oout)
{
    extern __shared__ char smem[];
    const uint32_t smem_base = smem_to_u32(smem);
    const int tid = threadIdx.x;
    const int wid = tid >> 5, lane = tid & 31;
    const int wm = wid & 3, wn = wid >> 2;   /* 4x4 warps, warp tile 64x32 */

    int p, b;
    const __nv_bfloat16 *Ah, *Al;
    const float* bias;
    if (MODE == 0) {
        p = blockIdx.z >> 2; b = blockIdx.z & 3;
        Ah = g_Xh + (size_t)p * TTOK * EMBED;
        Al = g_Xl + (size_t)p * TTOK * EMBED;
        bias = (p == 0) ? bias0 : (p == 1) ? bias1 : bias2;
    } else {
        p = 3; b = blockIdx.z;
        Ah = g_AOh; Al = g_AOl;
        bias = bias0;
    }
    const __nv_bfloat16* Bh = g_Wh + (size_t)(p * NB + b) * EBS * EBS;
    const __nv_bfloat16* Bl = g_Wl + (size_t)(p * NB + b) * EBS * EBS;
    const int m0 = blockIdx.y * 256, n0 = blockIdx.x * 128;

    /* A loader: row = tid>>1 (0..255), 64B half; 4 x cpa16 per tile */
    const int arow_i = tid >> 1;
    const int aseg = (tid & 1) * 32;          /* bf16 elems */
    const __nv_bfloat16* Arow_h = Ah + (size_t)(m0 + arow_i) * EMBED + b * EBS + aseg;
    const __nv_bfloat16* Arow_l = Al + (size_t)(m0 + arow_i) * EMBED + b * EBS + aseg;
    uint32_t swa[4];
#pragma unroll
    for (int j = 0; j < 4; j++)
        swa[j] = SMEM_SWIZZLE_128B((uint32_t)(arow_i * 128 + (aseg + j * 8) * 2));

    /* B loader: row = tid>>2 (0..127), 32B quarter; 2 x cpa16 per tile */
    const int brow_i = tid >> 2;
    const int bseg = (tid & 3) * 16;
    const __nv_bfloat16* Brow_h = Bh + (size_t)(n0 + brow_i) * EBS + bseg;
    const __nv_bfloat16* Brow_l = Bl + (size_t)(n0 + brow_i) * EBS + bseg;
    uint32_t swb[2];
#pragma unroll
    for (int j = 0; j < 2; j++)
        swb[j] = SMEM_SWIZZLE_128B((uint32_t)(brow_i * 128 + (bseg + j * 8) * 2));

#define MM_ISSUE(cc, buf)                                                      \
    do {                                                                       \
        const int _co = (cc) * KCHUNK;                                         \
        const uint32_t _bb = smem_base + (buf) * MMBUF;                        \
        _Pragma("unroll")                                                      \
        for (int j = 0; j < 4; j++) {                                          \
            cpa16(_bb + swa[j], Arow_h + _co + j * 8);                         \
            cpa16(_bb + A_TILE + swa[j], Arow_l + _co + j * 8);                \
        }                                                                      \
        _Pragma("unroll")                                                      \
        for (int j = 0; j < 2; j++) {                                          \
            cpa16(_bb + 2 * A_TILE + swb[j], Brow_h + _co + j * 8);            \
            cpa16(_bb + 2 * A_TILE + B_TILE + swb[j], Brow_l + _co + j * 8);   \
        }                                                                      \
    } while (0)

    MM_ISSUE(0, 0);
    CP_COMMIT();
    MM_ISSUE(1, 1);
    CP_COMMIT();

    const int a_row = (lane & 15);
    const int a_c16 = (lane >> 4) * 16;
    const int b_row = (lane & 7) + ((lane >> 4) << 3);
    const int b_c16 = ((lane >> 3) & 1) * 16;

    float acc[4][4][4];
#pragma unroll
    for (int mf = 0; mf < 4; mf++)
#pragma unroll
        for (int nf = 0; nf < 4; nf++)
#pragma unroll
            for (int r = 0; r < 4; r++) acc[mf][nf][r] = 0.f;

    for (int c = 0; c < NCHUNKS; c++) {
        CP_WAIT1();
        __syncthreads();
        const uint32_t bb = smem_base + (c & 1) * MMBUF;
        const uint32_t tAh = bb, tAl = bb + A_TILE;
        const uint32_t tBh = bb + 2 * A_TILE, tBl = bb + 2 * A_TILE + B_TILE;

#pragma unroll
        for (int ks = 0; ks < 4; ks++) {
            uint32_t ah[4][4], al[4][4];
#pragma unroll
            for (int mf = 0; mf < 4; mf++) {
                const uint32_t off = (uint32_t)((wm * 64 + mf * 16 + a_row) * 128
                                                + ks * 32 + a_c16);
                const uint32_t swo = SMEM_SWIZZLE_128B(off);
                ldsm4(ah[mf], tAh + swo);
                ldsm4(al[mf], tAl + swo);
            }
            uint32_t bh[8];
#pragma unroll
            for (int np = 0; np < 2; np++) {
                const uint32_t off = (uint32_t)((wn * 32 + np * 16 + b_row) * 128
                                                + ks * 32 + b_c16);
                ldsm4(&bh[np * 4], tBh + SMEM_SWIZZLE_128B(off));
            }
#pragma unroll
            for (int mf = 0; mf < 4; mf++)
#pragma unroll
                for (int nf = 0; nf < 4; nf++)
                    mma16816(acc[mf][nf], ah[mf], &bh[nf * 2]);
#pragma unroll
            for (int mf = 0; mf < 4; mf++)
#pragma unroll
                for (int nf = 0; nf < 4; nf++)
                    mma16816(acc[mf][nf], al[mf], &bh[nf * 2]);
            uint32_t bl[8];
#pragma unroll
            for (int np = 0; np < 2; np++) {
                const uint32_t off = (uint32_t)((wn * 32 + np * 16 + b_row) * 128
                                                + ks * 32 + b_c16);
                ldsm4(&bl[np * 4], tBl + SMEM_SWIZZLE_128B(off));
            }
#pragma unroll
            for (int mf = 0; mf < 4; mf++)
#pragma unroll
                for (int nf = 0; nf < 4; nf++)
                    mma16816(acc[mf][nf], ah[mf], &bl[nf * 2]);
        }
        __syncthreads();
        if (c + 2 < NCHUNKS)
            MM_ISSUE(c + 2, c & 1);
        CP_COMMIT();
    }
    CP_WAIT0();
    __syncthreads();

    float* stg = (float*)smem;  /* [256][SS] = 135 KB */
    const int gr = lane >> 2, c2 = (lane & 3) * 2;
#pragma unroll
    for (int mf = 0; mf < 4; mf++) {
        const int row0 = wm * 64 + mf * 16 + gr;
#pragma unroll
        for (int nf = 0; nf < 4; nf++) {
            const int col = wn * 32 + nf * 8 + c2;
            *(float2*)&stg[row0 * SS + col]       = make_float2(acc[mf][nf][0], acc[mf][nf][1]);
            *(float2*)&stg[(row0 + 8) * SS + col] = make_float2(acc[mf][nf][2], acc[mf][nf][3]);
        }
    }
    __syncthreads();

    if (MODE == 0) {
        const int n = m0 >> 10, s0 = m0 & (SEQ - 1);
        const int h0 = n0 >> 6;
        if (p >= 1) {
            __nv_bfloat16* oh = (p == 1) ? g_Kh : g_Qh;
            __nv_bfloat16* ol = (p == 1) ? g_Kl : g_Ql;
#pragma unroll
            for (int it = 0; it < 16; it++) {
                const int flat = tid + it * 512;
                const int srow = flat >> 5;
                const int rem = flat & 31;
                const int hh = rem >> 4, dq = (rem & 15) * 4;
                const int ocol = hh * 64 + dq;
                float hi[4], lo[4];
#pragma unroll
                for (int j = 0; j < 4; j++) {
                    const float v = stg[srow * SS + ocol + j]
                                    + bias[b * EBS + n0 + ocol + j];
                    splitf(v, hi[j], lo[j]);
                }
                uint2 hv, lv;
                hv.x = packbf2(hi[0], hi[1]); hv.y = packbf2(hi[2], hi[3]);
                lv.x = packbf2(lo[0], lo[1]); lv.y = packbf2(lo[2], lo[3]);
                const size_t gidx = (size_t)((n * NB + b) * HEADS + h0 + hh);
                const size_t off = (gidx * SEQ + s0 + srow) * HD + dq;
                *(uint2*)(oh + off) = hv;
                *(uint2*)(ol + off) = lv;
            }
        } else {
            /* V: bf16 hi/lo transposed [g][d][s]; 256 s-rows per tile */
            const int dcol = tid >> 2;
            const int sq = (tid & 3) * 64;
            const int hh = dcol >> 6, dl = dcol & 63;
            const size_t gidx = (size_t)((n * NB + b) * HEADS + h0 + hh);
            const float bb = bias[b * EBS + n0 + dcol];
            __nv_bfloat16* oh = g_Vth + (gidx * HD + dl) * SEQ + s0 + sq;
            __nv_bfloat16* ol = g_Vtl + (gidx * HD + dl) * SEQ + s0 + sq;
#pragma unroll
            for (int blk = 0; blk < 16; blk++) {
                float hi[4], lo[4];
#pragma unroll
                for (int j = 0; j < 4; j++) {
                    const float v = stg[(sq + blk * 4 + j) * SS + dcol] + bb;
                    splitf(v, hi[j], lo[j]);
                }
                uint2 hv, lv;
                hv.x = packbf2(hi[0], hi[1]); hv.y = packbf2(hi[2], hi[3]);
                lv.x = packbf2(lo[0], lo[1]); lv.y = packbf2(lo[2], lo[3]);
                *(uint2*)(oh + blk * 4) = hv;
                *(uint2*)(ol + blk * 4) = lv;
            }
        }
    } else {
#pragma unroll
        for (int it = 0; it < 16; it++) {
            const int flat = tid + it * 512;
            const int srow = flat >> 5;
            const int oq = (flat & 31) * 4;
            float4 v;
            v.x = stg[srow * SS + oq + 0] + bias[b * EBS + n0 + oq + 0];
            v.y = stg[srow * SS + oq + 1] + bias[b * EBS + n0 + oq + 1];
            v.z = stg[srow * SS + oq + 2] + bias[b * EBS + n0 + oq + 2];
            v.w = stg[srow * SS + oq + 3] + bias[b * EBS + n0 + oq + 3];
            *(float4*)(oout + (size_t)(m0 + srow) * EMBED + b * EBS + n0 + oq) = v;
        }
    }
}

/* ================================================================== */
/* Energy v2 (unchanged): Q resident, K cp.async streamed.             */
/* ================================================================== */
#define TILE16K 16384
#define SMEM_ENERGY 98304

__global__ __launch_bounds__(256, 2) void energy_mma_kernel()
{
    extern __shared__ char smem[];
    const uint32_t smem_base = smem_to_u32(smem);
    const int tid = threadIdx.x;
    const int wid = tid >> 5, lane = tid & 31;
    const int wm = wid & 1, wn = wid >> 1;

    const int g  = blockIdx.y;
    const int qt = blockIdx.x;
    const int q0 = qt * 128;
    const int n = g >> 5;

    const uint32_t tQh = smem_base;
    const uint32_t tQl = smem_base + TILE16K;

    const int lrow = tid >> 1;
    const int lhalf = (tid & 1) * 32;
    uint32_t sw[4];
#pragma unroll
    for (int gix = 0; gix < 4; gix++)
        sw[gix] = SMEM_SWIZZLE_128B((uint32_t)(lrow * 128 + (lhalf + gix * 8) * 2));

    const __nv_bfloat16* qh = g_Qh + ((size_t)g * SEQ + q0 + lrow) * HD + lhalf;
    const __nv_bfloat16* ql = g_Ql + ((size_t)g * SEQ + q0 + lrow) * HD + lhalf;
    const __nv_bfloat16* khb = g_Kh + ((size_t)g * SEQ + lrow) * HD + lhalf;
    const __nv_bfloat16* klb = g_Kl + ((size_t)g * SEQ + lrow) * HD + lhalf;

#pragma unroll
    for (int gix = 0; gix < 4; gix++) {
        cpa16(tQh + sw[gix], qh + gix * 8);
        cpa16(tQl + sw[gix], ql + gix * 8);
    }
    {
        const uint32_t kb = smem_base + 2 * TILE16K;
#pragma unroll
        for (int gix = 0; gix < 4; gix++) {
            cpa16(kb + sw[gix], khb + gix * 8);
            cpa16(kb + TILE16K + sw[gix], klb + gix * 8);
        }
    }
    CP_COMMIT();
    {
        const uint32_t kb = smem_base + 4 * TILE16K;
        const size_t so = (size_t)128 * HD;
#pragma unroll
        for (int gix = 0; gix < 4; gix++) {
            cpa16(kb + sw[gix], khb + so + gix * 8);
            cpa16(kb + TILE16K + sw[gix], klb + so + gix * 8);
        }
    }
    CP_COMMIT();

    const int a_row = (lane & 15);
    const int a_c16 = (lane >> 4) * 16;
    const int b_row = (lane & 7) + ((lane >> 4) << 3);
    const int b_c16 = ((lane >> 3) & 1) * 16;
    const int gr = lane >> 2, c2 = (lane & 3) * 2;

    const uint32_t* Mbn = g_Mb + (size_t)n * SEQ * 32;
    __nv_bfloat16* Egh = g_Eh + (size_t)g * SEQ * SEQ;
    __nv_bfloat16* Egl = g_El + (size_t)g * SEQ * SEQ;

    for (int c = 0; c < 8; c++) {
        CP_WAIT1();
        __syncthreads();
        const uint32_t tKh = smem_base + (2 + 2 * (c & 1)) * TILE16K;
        const uint32_t tKl = tKh + TILE16K;

        float acc[4][4][4];
#pragma unroll
        for (int mf = 0; mf < 4; mf++)
#pragma unroll
            for (int nf = 0; nf < 4; nf++)
#pragma unroll
                for (int r = 0; r < 4; r++) acc[mf][nf][r] = 0.f;

#pragma unroll
        for (int ks = 0; ks < 4; ks++) {
            uint32_t ah[4][4], al[4][4];
#pragma unroll
            for (int mf = 0; mf < 4; mf++) {
                const uint32_t off = (uint32_t)((wm * 64 + mf * 16 + a_row) * 128
                                                + ks * 32 + a_c16);
                const uint32_t swo = SMEM_SWIZZLE_128B(off);
                ldsm4(ah[mf], tQh + swo);
                ldsm4(al[mf], tQl + swo);
            }
            uint32_t bh[8];
#pragma unroll
            for (int np = 0; np < 2; np++) {
                const uint32_t off = (uint32_t)((wn * 32 + np * 16 + b_row) * 128
                                                + ks * 32 + b_c16);
                ldsm4(&bh[np * 4], tKh + SMEM_SWIZZLE_128B(off));
            }
#pragma unroll
            for (int mf = 0; mf < 4; mf++)
#pragma unroll
                for (int nf = 0; nf < 4; nf++)
                    mma16816(acc[mf][nf], ah[mf], &bh[nf * 2]);
#pragma unroll
            for (int mf = 0; mf < 4; mf++)
#pragma unroll
                for (int nf = 0; nf < 4; nf++)
                    mma16816(acc[mf][nf], al[mf], &bh[nf * 2]);
            uint32_t bl[8];
#pragma unroll
            for (int np = 0; np < 2; np++) {
                const uint32_t off = (uint32_t)((wn * 32 + np * 16 + b_row) * 128
                                                + ks * 32 + b_c16);
                ldsm4(&bl[np * 4], tKl + SMEM_SWIZZLE_128B(off));
            }
#pragma unroll
            for (int mf = 0; mf < 4; mf++)
#pragma unroll
                for (int nf = 0; nf < 4; nf++)
                    mma16816(acc[mf][nf], ah[mf], &bl[nf * 2]);
        }
        __syncthreads();

        if (c + 2 < 8) {
            const uint32_t kb = smem_base + (2 + 2 * (c & 1)) * TILE16K;
            const size_t so = (size_t)(c + 2) * 128 * HD;
#pragma unroll
            for (int gix = 0; gix < 4; gix++) {
                cpa16(kb + sw[gix], khb + so + gix * 8);
                cpa16(kb + TILE16K + sw[gix], klb + so + gix * 8);
            }
        }
        CP_COMMIT();

        const int l0 = c * 128;
        const int cw = c * 4 + wn;
        float csum[4][2];
#pragma unroll
        for (int nf = 0; nf < 4; nf++) { csum[nf][0] = 0.f; csum[nf][1] = 0.f; }

#pragma unroll
        for (int mf = 0; mf < 4; mf++) {
#pragma unroll
            for (int half = 0; half < 2; half++) {
                const int q = q0 + wm * 64 + mf * 16 + gr + half * 8;
                const uint32_t w = Mbn[q * 32 + cw];
#pragma unroll
                for (int nf = 0; nf < 4; nf++) {
                    const int col = l0 + wn * 32 + nf * 8 + c2;
                    const uint32_t bits = (w >> (nf * 8 + c2)) & 3u;
                    float2 e;
                    e.x = (bits & 1u) ? __expf(acc[mf][nf][half * 2 + 0] * 0.125f) : 0.f;
                    e.y = (bits & 2u) ? __expf(acc[mf][nf][half * 2 + 1] * 0.125f) : 0.f;
                    float h0, lo0, h1, lo1;
                    splitf(e.x, h0, lo0);
                    splitf(e.y, h1, lo1);
                    *(uint32_t*)(Egh + (size_t)q * SEQ + col) = packbf2(h0, h1);
                    *(uint32_t*)(Egl + (size_t)q * SEQ + col) = packbf2(lo0, lo1);
                    csum[nf][0] += e.x;
                    csum[nf][1] += e.y;
                }
            }
        }
        float* Zp = g_Zp[qt * 2 + wm] + g * SEQ;
#pragma unroll
        for (int nf = 0; nf < 4; nf++) {
#pragma unroll
            for (int cc = 0; cc < 2; cc++) {
                float v = csum[nf][cc];
                v += __shfl_xor_sync(0xffffffffu, v, 4);
                v += __shfl_xor_sync(0xffffffffu, v, 8);
                v += __shfl_xor_sync(0xffffffffu, v, 16);
                if (gr == 0)
                    Zp[l0 + wn * 32 + nf * 8 + c2 + cc] = v;
            }
        }
    }
}

/* ================================================================== */
__global__ __launch_bounds__(256) void zred_kernel()
{
    const int i = blockIdx.x * 256 + threadIdx.x;
    float z = 0.f;
#pragma unroll
    for (int s = 0; s < 16; s++)
        z += g_Zp[s][i];
    g_Zi[i] = (z > 0.f) ? (1.f / z) : 0.f;
}

/* ================================================================== */
__global__ __launch_bounds__(256) void vscale_kernel()
{
    const size_t e = ((size_t)blockIdx.x * 256 + threadIdx.x) * 8;
    const int g = (int)(e / ((size_t)HD * SEQ));
    const int s = (int)(e % SEQ);
    float4 z0 = *(const float4*)(g_Zi + g * SEQ + s);
    float4 z1 = *(const float4*)(g_Zi + g * SEQ + s + 4);
    const float zz[8] = {z0.x, z0.y, z0.z, z0.w, z1.x, z1.y, z1.z, z1.w};
    uint4 vh = *(const uint4*)(g_Vth + e);
    uint4 vl = *(const uint4*)(g_Vtl + e);
    const uint32_t hw[4] = {vh.x, vh.y, vh.z, vh.w};
    const uint32_t lw[4] = {vl.x, vl.y, vl.z, vl.w};
    uint32_t oh[4], ol[4];
#pragma unroll
    for (int j = 0; j < 4; j++) {
        float2 fh = upk(hw[j]);
        float2 fl = upk(lw[j]);
        const float a = (fh.x + fl.x) * zz[2 * j];
        const float b = (fh.y + fl.y) * zz[2 * j + 1];
        float ah, alo, bh, blo;
        splitf(a, ah, alo);
        splitf(b, bh, blo);
        oh[j] = packbf2(ah, bh);
        ol[j] = packbf2(alo, blo);
    }
    *(uint4*)(g_Vth + e) = make_uint4(oh[0], oh[1], oh[2], oh[3]);
    *(uint4*)(g_Vtl + e) = make_uint4(ol[0], ol[1], ol[2], ol[3]);
}

/* ================================================================== */
/* AV v2 (unchanged): pure GEMM, cp.async double-buffered.             */
/* ================================================================== */
#define AVBUF 49152
#define SMEM_AV (2 * AVBUF)

__global__ __launch_bounds__(256, 2) void av_mma_kernel()
{
    extern __shared__ char smem[];
    const uint32_t smem_base = smem_to_u32(smem);
    const int tid = threadIdx.x;
    const int wid = tid >> 5, lane = tid & 31;
    const int wm = wid >> 1, wn = wid & 1;

    const int g  = blockIdx.y;
    const int q0 = blockIdx.x * 128;

    const int erow = tid >> 1;
    const int ebyte = (tid & 1) * 64;
    const __nv_bfloat16* ehb = g_Eh + ((size_t)g * SEQ + q0 + erow) * SEQ + ebyte / 2;
    const __nv_bfloat16* elb = g_El + ((size_t)g * SEQ + q0 + erow) * SEQ + ebyte / 2;
    uint32_t esw[4];
#pragma unroll
    for (int gix = 0; gix < 4; gix++)
        esw[gix] = SMEM_SWIZZLE_128B((uint32_t)(erow * 128 + ebyte + gix * 16));

    const int vrow = tid >> 2;
    const int vbyte = (tid & 3) * 32;
    const __nv_bfloat16* vhb = g_Vth + ((size_t)g * HD + vrow) * SEQ + vbyte / 2;
    const __nv_bfloat16* vlb = g_Vtl + ((size_t)g * HD + vrow) * SEQ + vbyte / 2;
    uint32_t vsw[2];
#pragma unroll
    for (int j = 0; j < 2; j++)
        vsw[j] = SMEM_SWIZZLE_128B((uint32_t)(vrow * 128 + vbyte + j * 16));

#define AV_ISSUE(cc, buf)                                                      \
    do {                                                                       \
        const int _l0 = (cc) * 64;                                             \
        const uint32_t _bb = smem_base + (buf) * AVBUF;                        \
        _Pragma("unroll")                                                      \
        for (int gix = 0; gix < 4; gix++) {                                    \
            cpa16(_bb + esw[gix], ehb + _l0 + gix * 8);                        \
            cpa16(_bb + 16384 + esw[gix], elb + _l0 + gix * 8);                \
        }                                                                      \
        _Pragma("unroll")                                                      \
        for (int j = 0; j < 2; j++) {                                          \
            cpa16(_bb + 32768 + vsw[j], vhb + _l0 + j * 8);                    \
            cpa16(_bb + 40960 + vsw[j], vlb + _l0 + j * 8);                    \
        }                                                                      \
    } while (0)

    AV_ISSUE(0, 0);
    CP_COMMIT();
    AV_ISSUE(1, 1);
    CP_COMMIT();

    const int a_row = (lane & 15);
    const int a_c16 = (lane >> 4) * 16;
    const int b_row = (lane & 7) + ((lane >> 4) << 3);
    const int b_c16 = ((lane >> 3) & 1) * 16;

    float acc[2][4][4];
#pragma unroll
    for (int mf = 0; mf < 2; mf++)
#pragma unroll
        for (int nf = 0; nf < 4; nf++)
#pragma unroll
            for (int r = 0; r < 4; r++) acc[mf][nf][r] = 0.f;

    for (int c = 0; c < 16; c++) {
        CP_WAIT1();
        __syncthreads();
        const uint32_t bb = smem_base + (c & 1) * AVBUF;
        const uint32_t tEh = bb, tEl = bb + 16384;
        const uint32_t tVh = bb + 32768, tVl = bb + 40960;

#pragma unroll
        for (int ks = 0; ks < 4; ks++) {
            uint32_t ah[2][4], al[2][4];
#pragma unroll
            for (int mf = 0; mf < 2; mf++) {
                const uint32_t off = (uint32_t)((wm * 32 + mf * 16 + a_row) * 128
                                                + ks * 32 + a_c16);
                const uint32_t swo = SMEM_SWIZZLE_128B(off);
                ldsm4(ah[mf], tEh + swo);
                ldsm4(al[mf], tEl + swo);
            }
            uint32_t bh[8];
#pragma unroll
            for (int np = 0; np < 2; np++) {
                const uint32_t off = (uint32_t)((wn * 32 + np * 16 + b_row) * 128
                                                + ks * 32 + b_c16);
                ldsm4(&bh[np * 4], tVh + SMEM_SWIZZLE_128B(off));
            }
#pragma unroll
            for (int mf = 0; mf < 2; mf++)
#pragma unroll
                for (int nf = 0; nf < 4; nf++)
                    mma16816(acc[mf][nf], ah[mf], &bh[nf * 2]);
#pragma unroll
            for (int mf = 0; mf < 2; mf++)
#pragma unroll
                for (int nf = 0; nf < 4; nf++)
                    mma16816(acc[mf][nf], al[mf], &bh[nf * 2]);
            uint32_t bl[8];
#pragma unroll
            for (int np = 0; np < 2; np++) {
                const uint32_t off = (uint32_t)((wn * 32 + np * 16 + b_row) * 128
                                                + ks * 32 + b_c16);
                ldsm4(&bl[np * 4], tVl + SMEM_SWIZZLE_128B(off));
            }
#pragma unroll
            for (int mf = 0; mf < 2; mf++)
#pragma unroll
                for (int nf = 0; nf < 4; nf++)
                    mma16816(acc[mf][nf], ah[mf], &bl[nf * 2]);
        }
        __syncthreads();
        if (c + 2 < 16)
            AV_ISSUE(c + 2, c & 1);
        CP_COMMIT();
    }

    const int n = g >> 5, b = (g >> 3) & 3, hd = g & 7;
    const int gr = lane >> 2, c2 = (lane & 3) * 2;
#pragma unroll
    for (int mf = 0; mf < 2; mf++) {
#pragma unroll
        for (int nf = 0; nf < 4; nf++) {
            const int d = wn * 32 + nf * 8 + c2;
#pragma unroll
            for (int half = 0; half < 2; half++) {
                const int q = q0 + wm * 32 + mf * 16 + gr + half * 8;
                const size_t t = (size_t)(n * SEQ + q);
                const size_t off = t * EMBED + b * EBS + hd * HD + d;
                float h0, l0f, h1, l1;
                splitf(acc[mf][nf][half * 2 + 0], h0, l0f);
                splitf(acc[mf][nf][half * 2 + 1], h1, l1);
                *(uint32_t*)(g_AOh + off) = packbf2(h0, h1);
                *(uint32_t*)(g_AOl + off) = packbf2(l0f, l1);
            }
        }
    }
}

/* ------------------------------------------------------------------ */
extern "C" void kernel_launch(void* const* d_in, const int* in_sizes, int n_in,
                              void* d_out, int out_size)
{
    const float* values = (const float*)d_in[0];
    const float* keys   = (const float*)d_in[1];
    const float* query  = (const float*)d_in[2];
    const int*   mask   = (const int*)d_in[3];
    const float* Wv = (const float*)d_in[4];
    const float* bv = (const float*)d_in[5];
    const float* Wk = (const float*)d_in[6];
    const float* bk = (const float*)d_in[7];
    const float* Wq = (const float*)d_in[8];
    const float* bq = (const float*)d_in[9];
    const float* Wo = (const float*)d_in[10];
    const float* bo = (const float*)d_in[11];
    float* out = (float*)d_out;

    cudaFuncSetAttribute(mm_kernel<0>, cudaFuncAttributeMaxDynamicSharedMemorySize,
                         SMEM_GEMM_TOTAL);
    cudaFuncSetAttribute(mm_kernel<1>, cudaFuncAttributeMaxDynamicSharedMemorySize,
                         SMEM_GEMM_TOTAL);
    cudaFuncSetAttribute(energy_mma_kernel, cudaFuncAttributeMaxDynamicSharedMemorySize,
                         SMEM_ENERGY);
    cudaFuncSetAttribute(av_mma_kernel, cudaFuncAttributeMaxDynamicSharedMemorySize,
                         SMEM_AV);

    /* converts */
    dim3 gx((TTOK * EMBED) / (256 * 4), 3);
    convx_kernel<<<gx, 256>>>(values, keys, query);
    dim3 gw(EBS / 32, EBS / 32, 16);
    convw_kernel<<<gw, dim3(32, 8)>>>(Wv, Wk, Wq, Wo);
    convm_kernel<<<(NBATCH * SEQ) / 8, 256>>>(mask);

    /* fused qkv projections (tensor, 512 threads, 256x128 tile) */
    dim3 gqkv(EBS / 128, TTOK / 256, 12);
    mm_kernel<0><<<gqkv, 512, SMEM_GEMM_TOTAL>>>(bv, bk, bq, nullptr);

    /* energy + exp + column partial sums (tensor, pipelined) */
    dim3 ge(SEQ / 128, NG);
    energy_mma_kernel<<<ge, 256, SMEM_ENERGY>>>();

    /* reduce partials -> 1/Z, fold into V */
    zred_kernel<<<(NG * SEQ) / 256, 256>>>();
    vscale_kernel<<<(NG * HD * SEQ) / (256 * 8), 256>>>();

    /* AV (tensor, pipelined) */
    dim3 ga(SEQ / 128, NG);
    av_mma_kernel<<<ga, 256, SMEM_AV>>>();

    /* output projection (tensor, 512 threads, 256x128 tile) */
    dim3 go(EBS / 128, TTOK / 256, NB);
    mm_kernel<1><<<go, 512, SMEM_GEMM_TOTAL>>>(bo, nullptr, nullptr, out);
}

// round 16
// speedup vs baseline: 1.0301x; 1.0301x over previous
#include <cuda_runtime.h>
#include <cuda_bf16.h>
#include <math.h>
#include <stdint.h>

#define NBATCH 4
#define SEQ    1024
#define EMBED  2048
#define EBS    512
#define NB     4
#define HEADS  8
#define HD     64
#define TTOK   (NBATCH * SEQ)        /* 4096 tokens */
#define NG     (NBATCH * NB * HEADS) /* 128 (n,b,h) heads */

typedef unsigned long long u64;

#define SMEM_SWIZZLE_128B(off) ((off) ^ (((off) >> 3) & 0x70))

/* ================================================================== */
/* Tensor / async helpers (sm_80 path: legal on base sm_103 target)    */
/* ================================================================== */
__device__ __forceinline__ uint32_t smem_to_u32(const void* p) {
    uint32_t a;
    asm("{ .reg .u64 t; cvta.to.shared.u64 t, %1; cvt.u32.u64 %0, t; }"
        : "=r"(a) : "l"(p));
    return a;
}
__device__ __forceinline__ void ldsm4(uint32_t* r, uint32_t addr) {
    asm volatile("ldmatrix.sync.aligned.m8n8.x4.shared.b16 {%0,%1,%2,%3}, [%4];"
                 : "=r"(r[0]), "=r"(r[1]), "=r"(r[2]), "=r"(r[3]) : "r"(addr));
}
__device__ __forceinline__ void mma16816(float* d, const uint32_t* a,
                                         const uint32_t* b) {
    asm volatile(
        "mma.sync.aligned.m16n8k16.row.col.f32.bf16.bf16.f32 "
        "{%0,%1,%2,%3}, {%4,%5,%6,%7}, {%8,%9}, {%0,%1,%2,%3};"
        : "+f"(d[0]), "+f"(d[1]), "+f"(d[2]), "+f"(d[3])
        : "r"(a[0]), "r"(a[1]), "r"(a[2]), "r"(a[3]), "r"(b[0]), "r"(b[1]));
}
__device__ __forceinline__ void cpa16(uint32_t dst, const void* src) {
    asm volatile("cp.async.cg.shared.global [%0], [%1], 16;"
                 :: "r"(dst), "l"(src) : "memory");
}
#define CP_COMMIT() asm volatile("cp.async.commit_group;" ::: "memory")
#define CP_WAIT1()  asm volatile("cp.async.wait_group 1;" ::: "memory")
#define CP_WAIT0()  asm volatile("cp.async.wait_group 0;" ::: "memory")
__device__ __forceinline__ uint32_t packbf2(float a, float b) {
    __nv_bfloat162 p = __floats2bfloat162_rn(a, b);
    return *(uint32_t*)&p;
}
__device__ __forceinline__ void splitf(float v, float& hi, float& lo) {
    __nv_bfloat16 hb = __float2bfloat16_rn(v);
    hi = __bfloat162float(hb);
    lo = v - hi;
}
__device__ __forceinline__ float2 upk(uint32_t u) {
    __nv_bfloat162 b = *(__nv_bfloat162*)&u;
    return __bfloat1622float2(b);
}

/* ================================================================== */
/* Device scratch                                                      */
/* ================================================================== */
__device__ __align__(256) __nv_bfloat16 g_Eh[(size_t)NG * SEQ * SEQ]; /* 256 MB */
__device__ __align__(256) __nv_bfloat16 g_El[(size_t)NG * SEQ * SEQ]; /* 256 MB */
__device__ __align__(256) float g_Zp[16][NG * SEQ];
__device__ float g_Zi[NG * SEQ];
__device__ __align__(256) uint32_t g_Mb[NBATCH * SEQ * 32];           /* bit mask */
__device__ __align__(256) __nv_bfloat16 g_Xh[(size_t)3 * TTOK * EMBED];
__device__ __align__(256) __nv_bfloat16 g_Xl[(size_t)3 * TTOK * EMBED];
__device__ __align__(256) __nv_bfloat16 g_AOh[(size_t)TTOK * EMBED];
__device__ __align__(256) __nv_bfloat16 g_AOl[(size_t)TTOK * EMBED];
__device__ __align__(256) __nv_bfloat16 g_Wh[(size_t)4 * NB * EBS * EBS];
__device__ __align__(256) __nv_bfloat16 g_Wl[(size_t)4 * NB * EBS * EBS];
__device__ __align__(256) __nv_bfloat16 g_Qh[(size_t)NG * SEQ * HD];
__device__ __align__(256) __nv_bfloat16 g_Ql[(size_t)NG * SEQ * HD];
__device__ __align__(256) __nv_bfloat16 g_Kh[(size_t)NG * SEQ * HD];
__device__ __align__(256) __nv_bfloat16 g_Kl[(size_t)NG * SEQ * HD];
__device__ __align__(256) __nv_bfloat16 g_Vth[(size_t)NG * HD * SEQ]; /* [g][d][s] */
__device__ __align__(256) __nv_bfloat16 g_Vtl[(size_t)NG * HD * SEQ];

/* ================================================================== */
/* Converters                                                          */
/* ================================================================== */
__global__ __launch_bounds__(256) void convx_kernel(
    const float* __restrict__ V, const float* __restrict__ K,
    const float* __restrict__ Q)
{
    const int p = blockIdx.y;
    const float* src = (p == 0) ? V : (p == 1) ? K : Q;
    __nv_bfloat16* dh = g_Xh + (size_t)p * TTOK * EMBED;
    __nv_bfloat16* dl = g_Xl + (size_t)p * TTOK * EMBED;
    const size_t i = ((size_t)blockIdx.x * 256 + threadIdx.x) * 4;
    float4 v = *(const float4*)(src + i);
    float f[4] = {v.x, v.y, v.z, v.w};
    float hi[4], lo[4];
#pragma unroll
    for (int j = 0; j < 4; j++) splitf(f[j], hi[j], lo[j]);
    uint2 hv, lv;
    hv.x = packbf2(hi[0], hi[1]); hv.y = packbf2(hi[2], hi[3]);
    lv.x = packbf2(lo[0], lo[1]); lv.y = packbf2(lo[2], lo[3]);
    *(uint2*)(dh + i) = hv;
    *(uint2*)(dl + i) = lv;
}

__global__ __launch_bounds__(256) void convw_kernel(
    const float* __restrict__ Wv, const float* __restrict__ Wk,
    const float* __restrict__ Wq, const float* __restrict__ Wo)
{
    __shared__ float st[32][33];
    const int z = blockIdx.z;
    const int wi = z >> 2, b = z & 3;
    const float* W = ((wi == 0) ? Wv : (wi == 1) ? Wk : (wi == 2) ? Wq : Wo)
                     + (size_t)b * EBS * EBS;
    const int i0 = blockIdx.y * 32, o0 = blockIdx.x * 32;
    const int tx = threadIdx.x, ty = threadIdx.y;
#pragma unroll
    for (int kk = 0; kk < 4; kk++)
        st[ty + 8 * kk][tx] = W[(size_t)(i0 + ty + 8 * kk) * EBS + o0 + tx];
    __syncthreads();
    __nv_bfloat16* oh = g_Wh + (size_t)(wi * NB + b) * EBS * EBS;
    __nv_bfloat16* ol = g_Wl + (size_t)(wi * NB + b) * EBS * EBS;
#pragma unroll
    for (int kk = 0; kk < 4; kk++) {
        const float v = st[tx][ty + 8 * kk];
        float h, l;
        splitf(v, h, l);
        const size_t off = (size_t)(o0 + ty + 8 * kk) * EBS + i0 + tx;
        oh[off] = __float2bfloat16_rn(h);
        ol[off] = __float2bfloat16_rn(l);
    }
}

/* pack mask int32 -> bits */
__global__ __launch_bounds__(256) void convm_kernel(const int* __restrict__ mask)
{
    const int wid = threadIdx.x >> 5, lane = threadIdx.x & 31;
    const int r = blockIdx.x * 8 + wid;
    const int* row = mask + (size_t)r * SEQ;
    uint32_t* orow = g_Mb + (size_t)r * 32;
    for (int w = 0; w < 32; w++) {
        const int m = row[w * 32 + lane];
        const uint32_t bits = __ballot_sync(0xffffffffu, m != 0);
        if (lane == 0) orow[w] = bits;
    }
}

/* ================================================================== */
/* mma.sync bf16 3-split projection GEMM (R13 config: best).           */
/* 512 threads (16 warps as 4m x 4n, warp tile 32x32), 128x128 CTA     */
/* tile, K=512 in 8 chunks of 64, 3-stage cp.async ring, single        */
/* __syncthreads per chunk.                                            */
/* ================================================================== */
#define KCHUNK 64
#define NCHUNKS 8
#define TILE_BYTES 16384
#define MMBUF (4 * TILE_BYTES)            /* 64 KB per chunk buffer */
#define SS 132
#define SMEM_GEMM_TOTAL (3 * MMBUF)       /* 192 KB */

template <int MODE>
__global__ __launch_bounds__(512) void mm_kernel(
    const float* __restrict__ bias0, const float* __restrict__ bias1,
    const float* __restrict__ bias2, float* __restrict__ oout)
{
    extern __shared__ char smem[];
    const uint32_t smem_base = smem_to_u32(smem);
    const int tid = threadIdx.x;
    const int wid = tid >> 5, lane = tid & 31;
    const int wm = wid & 3, wn = wid >> 2;   /* 4x4 warp grid, 32x32 tiles */

    int p, b;
    const __nv_bfloat16 *Ah, *Al;
    const float* bias;
    if (MODE == 0) {
        p = blockIdx.z >> 2; b = blockIdx.z & 3;
        Ah = g_Xh + (size_t)p * TTOK * EMBED;
        Al = g_Xl + (size_t)p * TTOK * EMBED;
        bias = (p == 0) ? bias0 : (p == 1) ? bias1 : bias2;
    } else {
        p = 3; b = blockIdx.z;
        Ah = g_AOh; Al = g_AOl;
        bias = bias0;
    }
    const __nv_bfloat16* Bh = g_Wh + (size_t)(p * NB + b) * EBS * EBS;
    const __nv_bfloat16* Bl = g_Wl + (size_t)(p * NB + b) * EBS * EBS;
    const int m0 = blockIdx.y * 128, n0 = blockIdx.x * 128;

    /* loaders: 512 threads, each 32B per 16KB tile (2 x cpa16) */
    const int lrow = tid >> 2;
    const int lseg = (tid & 3) * 16;          /* bf16 elems */
    const __nv_bfloat16* Arow_h = Ah + (size_t)(m0 + lrow) * EMBED + b * EBS + lseg;
    const __nv_bfloat16* Arow_l = Al + (size_t)(m0 + lrow) * EMBED + b * EBS + lseg;
    const __nv_bfloat16* Brow_h = Bh + (size_t)(n0 + lrow) * EBS + lseg;
    const __nv_bfloat16* Brow_l = Bl + (size_t)(n0 + lrow) * EBS + lseg;
    uint32_t sw[2];
#pragma unroll
    for (int j = 0; j < 2; j++)
        sw[j] = SMEM_SWIZZLE_128B((uint32_t)(lrow * 128 + (lseg + j * 8) * 2));

#define MM_ISSUE(cc, buf)                                                      \
    do {                                                                       \
        const int _co = (cc) * KCHUNK;                                         \
        const uint32_t _bb = smem_base + (buf) * MMBUF;                        \
        _Pragma("unroll")                                                      \
        for (int j = 0; j < 2; j++) {                                          \
            cpa16(_bb + 0 * TILE_BYTES + sw[j], Arow_h + _co + j * 8);         \
            cpa16(_bb + 1 * TILE_BYTES + sw[j], Arow_l + _co + j * 8);         \
            cpa16(_bb + 2 * TILE_BYTES + sw[j], Brow_h + _co + j * 8);         \
            cpa16(_bb + 3 * TILE_BYTES + sw[j], Brow_l + _co + j * 8);         \
        }                                                                      \
    } while (0)

    MM_ISSUE(0, 0);
    CP_COMMIT();
    MM_ISSUE(1, 1);
    CP_COMMIT();

    const int a_row = (lane & 15);
    const int a_c16 = (lane >> 4) * 16;
    const int b_row = (lane & 7) + ((lane >> 4) << 3);
    const int b_c16 = ((lane >> 3) & 1) * 16;

    float acc[2][4][4];
#pragma unroll
    for (int mf = 0; mf < 2; mf++)
#pragma unroll
        for (int nf = 0; nf < 4; nf++)
#pragma unroll
            for (int r = 0; r < 4; r++) acc[mf][nf][r] = 0.f;

    int rbuf = 0;
    for (int c = 0; c < NCHUNKS; c++) {
        CP_WAIT1();
        __syncthreads();
        if (c + 2 < NCHUNKS) {
            const int ibuf = (rbuf + 2 >= 3) ? rbuf + 2 - 3 : rbuf + 2;
            MM_ISSUE(c + 2, ibuf);
        }
        CP_COMMIT();

        const uint32_t bb = smem_base + rbuf * MMBUF;
        const uint32_t tAh = bb, tAl = bb + TILE_BYTES;
        const uint32_t tBh = bb + 2 * TILE_BYTES, tBl = bb + 3 * TILE_BYTES;

#pragma unroll
        for (int ks = 0; ks < 4; ks++) {
            uint32_t ah[2][4], al[2][4];
#pragma unroll
            for (int mf = 0; mf < 2; mf++) {
                const uint32_t off = (uint32_t)((wm * 32 + mf * 16 + a_row) * 128
                                                + ks * 32 + a_c16);
                const uint32_t swo = SMEM_SWIZZLE_128B(off);
                ldsm4(ah[mf], tAh + swo);
                ldsm4(al[mf], tAl + swo);
            }
            uint32_t bh[8];
#pragma unroll
            for (int np = 0; np < 2; np++) {
                const uint32_t off = (uint32_t)((wn * 32 + np * 16 + b_row) * 128
                                                + ks * 32 + b_c16);
                ldsm4(&bh[np * 4], tBh + SMEM_SWIZZLE_128B(off));
            }
#pragma unroll
            for (int mf = 0; mf < 2; mf++)
#pragma unroll
                for (int nf = 0; nf < 4; nf++)
                    mma16816(acc[mf][nf], ah[mf], &bh[nf * 2]);
#pragma unroll
            for (int mf = 0; mf < 2; mf++)
#pragma unroll
                for (int nf = 0; nf < 4; nf++)
                    mma16816(acc[mf][nf], al[mf], &bh[nf * 2]);
            uint32_t bl[8];
#pragma unroll
            for (int np = 0; np < 2; np++) {
                const uint32_t off = (uint32_t)((wn * 32 + np * 16 + b_row) * 128
                                                + ks * 32 + b_c16);
                ldsm4(&bl[np * 4], tBl + SMEM_SWIZZLE_128B(off));
            }
#pragma unroll
            for (int mf = 0; mf < 2; mf++)
#pragma unroll
                for (int nf = 0; nf < 4; nf++)
                    mma16816(acc[mf][nf], ah[mf], &bl[nf * 2]);
        }
        rbuf = (rbuf + 1 >= 3) ? 0 : rbuf + 1;
    }
    CP_WAIT0();
    __syncthreads();

    float* stg = (float*)smem;  /* [128][SS] */
    const int gr = lane >> 2, c2 = (lane & 3) * 2;
#pragma unroll
    for (int mf = 0; mf < 2; mf++) {
        const int row0 = wm * 32 + mf * 16 + gr;
#pragma unroll
        for (int nf = 0; nf < 4; nf++) {
            const int col = wn * 32 + nf * 8 + c2;
            *(float2*)&stg[row0 * SS + col]       = make_float2(acc[mf][nf][0], acc[mf][nf][1]);
            *(float2*)&stg[(row0 + 8) * SS + col] = make_float2(acc[mf][nf][2], acc[mf][nf][3]);
        }
    }
    __syncthreads();

    if (MODE == 0) {
        const int n = m0 >> 10, s0 = m0 & (SEQ - 1);
        const int h0 = n0 >> 6;
        if (p >= 1) {
            __nv_bfloat16* oh = (p == 1) ? g_Kh : g_Qh;
            __nv_bfloat16* ol = (p == 1) ? g_Kl : g_Ql;
#pragma unroll
            for (int it = 0; it < 8; it++) {
                const int flat = tid + it * 512;
                const int srow = flat >> 5;
                const int rem = flat & 31;
                const int hh = rem >> 4, dq = (rem & 15) * 4;
                const int ocol = hh * 64 + dq;
                float hi[4], lo[4];
#pragma unroll
                for (int j = 0; j < 4; j++) {
                    const float v = stg[srow * SS + ocol + j]
                                    + bias[b * EBS + n0 + ocol + j];
                    splitf(v, hi[j], lo[j]);
                }
                uint2 hv, lv;
                hv.x = packbf2(hi[0], hi[1]); hv.y = packbf2(hi[2], hi[3]);
                lv.x = packbf2(lo[0], lo[1]); lv.y = packbf2(lo[2], lo[3]);
                const size_t gidx = (size_t)((n * NB + b) * HEADS + h0 + hh);
                const size_t off = (gidx * SEQ + s0 + srow) * HD + dq;
                *(uint2*)(oh + off) = hv;
                *(uint2*)(ol + off) = lv;
            }
        } else {
            /* V: bf16 hi/lo transposed [g][d][s] */
            const int dcol = tid >> 2;
            const int squarter = (tid & 3) * 32;
            const int hh = dcol >> 6, dl = dcol & 63;
            const size_t gidx = (size_t)((n * NB + b) * HEADS + h0 + hh);
            const float bb = bias[b * EBS + n0 + dcol];
            __nv_bfloat16* oh = g_Vth + (gidx * HD + dl) * SEQ + s0 + squarter;
            __nv_bfloat16* ol = g_Vtl + (gidx * HD + dl) * SEQ + s0 + squarter;
#pragma unroll
            for (int blk = 0; blk < 8; blk++) {
                float hi[4], lo[4];
#pragma unroll
                for (int j = 0; j < 4; j++) {
                    const float v = stg[(squarter + blk * 4 + j) * SS + dcol] + bb;
                    splitf(v, hi[j], lo[j]);
                }
                uint2 hv, lv;
                hv.x = packbf2(hi[0], hi[1]); hv.y = packbf2(hi[2], hi[3]);
                lv.x = packbf2(lo[0], lo[1]); lv.y = packbf2(lo[2], lo[3]);
                *(uint2*)(oh + blk * 4) = hv;
                *(uint2*)(ol + blk * 4) = lv;
            }
        }
    } else {
#pragma unroll
        for (int it = 0; it < 8; it++) {
            const int flat = tid + it * 512;
            const int srow = flat >> 5;
            const int oq = (flat & 31) * 4;
            float4 v;
            v.x = stg[srow * SS + oq + 0] + bias[b * EBS + n0 + oq + 0];
            v.y = stg[srow * SS + oq + 1] + bias[b * EBS + n0 + oq + 1];
            v.z = stg[srow * SS + oq + 2] + bias[b * EBS + n0 + oq + 2];
            v.w = stg[srow * SS + oq + 3] + bias[b * EBS + n0 + oq + 3];
            *(float4*)(oout + (size_t)(m0 + srow) * EMBED + b * EBS + n0 + oq) = v;
        }
    }
}

/* ================================================================== */
/* Energy v3: Q resident, K cp.async streamed; single barrier per      */
/* chunk (wait0 / sync / issue-next / mma / epilogue).                 */
/* ================================================================== */
#define TILE16K 16384
#define SMEM_ENERGY 98304

__global__ __launch_bounds__(256, 2) void energy_mma_kernel()
{
    extern __shared__ char smem[];
    const uint32_t smem_base = smem_to_u32(smem);
    const int tid = threadIdx.x;
    const int wid = tid >> 5, lane = tid & 31;
    const int wm = wid & 1, wn = wid >> 1;

    const int g  = blockIdx.y;
    const int qt = blockIdx.x;
    const int q0 = qt * 128;
    const int n = g >> 5;

    const uint32_t tQh = smem_base;
    const uint32_t tQl = smem_base + TILE16K;

    const int lrow = tid >> 1;
    const int lhalf = (tid & 1) * 32;
    uint32_t sw[4];
#pragma unroll
    for (int gix = 0; gix < 4; gix++)
        sw[gix] = SMEM_SWIZZLE_128B((uint32_t)(lrow * 128 + (lhalf + gix * 8) * 2));

    const __nv_bfloat16* qh = g_Qh + ((size_t)g * SEQ + q0 + lrow) * HD + lhalf;
    const __nv_bfloat16* ql = g_Ql + ((size_t)g * SEQ + q0 + lrow) * HD + lhalf;
    const __nv_bfloat16* khb = g_Kh + ((size_t)g * SEQ + lrow) * HD + lhalf;
    const __nv_bfloat16* klb = g_Kl + ((size_t)g * SEQ + lrow) * HD + lhalf;

    /* prologue: Q + K tile 0 in one group */
#pragma unroll
    for (int gix = 0; gix < 4; gix++) {
        cpa16(tQh + sw[gix], qh + gix * 8);
        cpa16(tQl + sw[gix], ql + gix * 8);
    }
    {
        const uint32_t kb = smem_base + 2 * TILE16K;
#pragma unroll
        for (int gix = 0; gix < 4; gix++) {
            cpa16(kb + sw[gix], khb + gix * 8);
            cpa16(kb + TILE16K + sw[gix], klb + gix * 8);
        }
    }
    CP_COMMIT();

    const int a_row = (lane & 15);
    const int a_c16 = (lane >> 4) * 16;
    const int b_row = (lane & 7) + ((lane >> 4) << 3);
    const int b_c16 = ((lane >> 3) & 1) * 16;
    const int gr = lane >> 2, c2 = (lane & 3) * 2;

    const uint32_t* Mbn = g_Mb + (size_t)n * SEQ * 32;
    __nv_bfloat16* Egh = g_Eh + (size_t)g * SEQ * SEQ;
    __nv_bfloat16* Egl = g_El + (size_t)g * SEQ * SEQ;

    for (int c = 0; c < 8; c++) {
        CP_WAIT0();
        __syncthreads();
        /* issue chunk c+1 into buffer ((c+1)&1) — consumed at c-1, free now */
        if (c + 1 < 8) {
            const uint32_t kb = smem_base + (2 + 2 * ((c + 1) & 1)) * TILE16K;
            const size_t so = (size_t)(c + 1) * 128 * HD;
#pragma unroll
            for (int gix = 0; gix < 4; gix++) {
                cpa16(kb + sw[gix], khb + so + gix * 8);
                cpa16(kb + TILE16K + sw[gix], klb + so + gix * 8);
            }
        }
        CP_COMMIT();

        const uint32_t tKh = smem_base + (2 + 2 * (c & 1)) * TILE16K;
        const uint32_t tKl = tKh + TILE16K;

        float acc[4][4][4];
#pragma unroll
        for (int mf = 0; mf < 4; mf++)
#pragma unroll
            for (int nf = 0; nf < 4; nf++)
#pragma unroll
                for (int r = 0; r < 4; r++) acc[mf][nf][r] = 0.f;

#pragma unroll
        for (int ks = 0; ks < 4; ks++) {
            uint32_t ah[4][4], al[4][4];
#pragma unroll
            for (int mf = 0; mf < 4; mf++) {
                const uint32_t off = (uint32_t)((wm * 64 + mf * 16 + a_row) * 128
                                                + ks * 32 + a_c16);
                const uint32_t swo = SMEM_SWIZZLE_128B(off);
                ldsm4(ah[mf], tQh + swo);
                ldsm4(al[mf], tQl + swo);
            }
            uint32_t bh[8];
#pragma unroll
            for (int np = 0; np < 2; np++) {
                const uint32_t off = (uint32_t)((wn * 32 + np * 16 + b_row) * 128
                                                + ks * 32 + b_c16);
                ldsm4(&bh[np * 4], tKh + SMEM_SWIZZLE_128B(off));
            }
#pragma unroll
            for (int mf = 0; mf < 4; mf++)
#pragma unroll
                for (int nf = 0; nf < 4; nf++)
                    mma16816(acc[mf][nf], ah[mf], &bh[nf * 2]);
#pragma unroll
            for (int mf = 0; mf < 4; mf++)
#pragma unroll
                for (int nf = 0; nf < 4; nf++)
                    mma16816(acc[mf][nf], al[mf], &bh[nf * 2]);
            uint32_t bl[8];
#pragma unroll
            for (int np = 0; np < 2; np++) {
                const uint32_t off = (uint32_t)((wn * 32 + np * 16 + b_row) * 128
                                                + ks * 32 + b_c16);
                ldsm4(&bl[np * 4], tKl + SMEM_SWIZZLE_128B(off));
            }
#pragma unroll
            for (int mf = 0; mf < 4; mf++)
#pragma unroll
                for (int nf = 0; nf < 4; nf++)
                    mma16816(acc[mf][nf], ah[mf], &bl[nf * 2]);
        }

        /* epilogue (register-only inputs; no barrier needed) */
        const int l0 = c * 128;
        const int cw = c * 4 + wn;
        float csum[4][2];
#pragma unroll
        for (int nf = 0; nf < 4; nf++) { csum[nf][0] = 0.f; csum[nf][1] = 0.f; }

#pragma unroll
        for (int mf = 0; mf < 4; mf++) {
#pragma unroll
            for (int half = 0; half < 2; half++) {
                const int q = q0 + wm * 64 + mf * 16 + gr + half * 8;
                const uint32_t w = Mbn[q * 32 + cw];
#pragma unroll
                for (int nf = 0; nf < 4; nf++) {
                    const int col = l0 + wn * 32 + nf * 8 + c2;
                    const uint32_t bits = (w >> (nf * 8 + c2)) & 3u;
                    float2 e;
                    e.x = (bits & 1u) ? __expf(acc[mf][nf][half * 2 + 0] * 0.125f) : 0.f;
                    e.y = (bits & 2u) ? __expf(acc[mf][nf][half * 2 + 1] * 0.125f) : 0.f;
                    float h0, lo0, h1, lo1;
                    splitf(e.x, h0, lo0);
                    splitf(e.y, h1, lo1);
                    *(uint32_t*)(Egh + (size_t)q * SEQ + col) = packbf2(h0, h1);
                    *(uint32_t*)(Egl + (size_t)q * SEQ + col) = packbf2(lo0, lo1);
                    csum[nf][0] += e.x;
                    csum[nf][1] += e.y;
                }
            }
        }
        float* Zp = g_Zp[qt * 2 + wm] + g * SEQ;
#pragma unroll
        for (int nf = 0; nf < 4; nf++) {
#pragma unroll
            for (int cc = 0; cc < 2; cc++) {
                float v = csum[nf][cc];
                v += __shfl_xor_sync(0xffffffffu, v, 4);
                v += __shfl_xor_sync(0xffffffffu, v, 8);
                v += __shfl_xor_sync(0xffffffffu, v, 16);
                if (gr == 0)
                    Zp[l0 + wn * 32 + nf * 8 + c2 + cc] = v;
            }
        }
    }
}

/* ================================================================== */
__global__ __launch_bounds__(256) void zred_kernel()
{
    const int i = blockIdx.x * 256 + threadIdx.x;
    float z = 0.f;
#pragma unroll
    for (int s = 0; s < 16; s++)
        z += g_Zp[s][i];
    g_Zi[i] = (z > 0.f) ? (1.f / z) : 0.f;
}

/* ================================================================== */
__global__ __launch_bounds__(256) void vscale_kernel()
{
    const size_t e = ((size_t)blockIdx.x * 256 + threadIdx.x) * 8;
    const int g = (int)(e / ((size_t)HD * SEQ));
    const int s = (int)(e % SEQ);
    float4 z0 = *(const float4*)(g_Zi + g * SEQ + s);
    float4 z1 = *(const float4*)(g_Zi + g * SEQ + s + 4);
    const float zz[8] = {z0.x, z0.y, z0.z, z0.w, z1.x, z1.y, z1.z, z1.w};
    uint4 vh = *(const uint4*)(g_Vth + e);
    uint4 vl = *(const uint4*)(g_Vtl + e);
    const uint32_t hw[4] = {vh.x, vh.y, vh.z, vh.w};
    const uint32_t lw[4] = {vl.x, vl.y, vl.z, vl.w};
    uint32_t oh[4], ol[4];
#pragma unroll
    for (int j = 0; j < 4; j++) {
        float2 fh = upk(hw[j]);
        float2 fl = upk(lw[j]);
        const float a = (fh.x + fl.x) * zz[2 * j];
        const float b = (fh.y + fl.y) * zz[2 * j + 1];
        float ah, alo, bh, blo;
        splitf(a, ah, alo);
        splitf(b, bh, blo);
        oh[j] = packbf2(ah, bh);
        ol[j] = packbf2(alo, blo);
    }
    *(uint4*)(g_Vth + e) = make_uint4(oh[0], oh[1], oh[2], oh[3]);
    *(uint4*)(g_Vtl + e) = make_uint4(ol[0], ol[1], ol[2], ol[3]);
}

/* ================================================================== */
/* AV v3: pure GEMM; single barrier per chunk (wait0/sync/issue/mma).  */
/* ================================================================== */
#define AVBUF 49152
#define SMEM_AV (2 * AVBUF)

__global__ __launch_bounds__(256, 2) void av_mma_kernel()
{
    extern __shared__ char smem[];
    const uint32_t smem_base = smem_to_u32(smem);
    const int tid = threadIdx.x;
    const int wid = tid >> 5, lane = tid & 31;
    const int wm = wid >> 1, wn = wid & 1;

    const int g  = blockIdx.y;
    const int q0 = blockIdx.x * 128;

    const int erow = tid >> 1;
    const int ebyte = (tid & 1) * 64;
    const __nv_bfloat16* ehb = g_Eh + ((size_t)g * SEQ + q0 + erow) * SEQ + ebyte / 2;
    const __nv_bfloat16* elb = g_El + ((size_t)g * SEQ + q0 + erow) * SEQ + ebyte / 2;
    uint32_t esw[4];
#pragma unroll
    for (int gix = 0; gix < 4; gix++)
        esw[gix] = SMEM_SWIZZLE_128B((uint32_t)(erow * 128 + ebyte + gix * 16));

    const int vrow = tid >> 2;
    const int vbyte = (tid & 3) * 32;
    const __nv_bfloat16* vhb = g_Vth + ((size_t)g * HD + vrow) * SEQ + vbyte / 2;
    const __nv_bfloat16* vlb = g_Vtl + ((size_t)g * HD + vrow) * SEQ + vbyte / 2;
    uint32_t vsw[2];
#pragma unroll
    for (int j = 0; j < 2; j++)
        vsw[j] = SMEM_SWIZZLE_128B((uint32_t)(vrow * 128 + vbyte + j * 16));

#define AV_ISSUE(cc, buf)                                                      \
    do {                                                                       \
        const int _l0 = (cc) * 64;                                             \
        const uint32_t _bb = smem_base + (buf) * AVBUF;                        \
        _Pragma("unroll")                                                      \
        for (int gix = 0; gix < 4; gix++) {                                    \
            cpa16(_bb + esw[gix], ehb + _l0 + gix * 8);                        \
            cpa16(_bb + 16384 + esw[gix], elb + _l0 + gix * 8);                \
        }                                                                      \
        _Pragma("unroll")                                                      \
        for (int j = 0; j < 2; j++) {                                          \
            cpa16(_bb + 32768 + vsw[j], vhb + _l0 + j * 8);                    \
            cpa16(_bb + 40960 + vsw[j], vlb + _l0 + j * 8);                    \
        }                                                                      \
    } while (0)

    AV_ISSUE(0, 0);
    CP_COMMIT();

    const int a_row = (lane & 15);
    const int a_c16 = (lane >> 4) * 16;
    const int b_row = (lane & 7) + ((lane >> 4) << 3);
    const int b_c16 = ((lane >> 3) & 1) * 16;

    float acc[2][4][4];
#pragma unroll
    for (int mf = 0; mf < 2; mf++)
#pragma unroll
        for (int nf = 0; nf < 4; nf++)
#pragma unroll
            for (int r = 0; r < 4; r++) acc[mf][nf][r] = 0.f;

    for (int c = 0; c < 16; c++) {
        CP_WAIT0();
        __syncthreads();
        if (c + 1 < 16)
            AV_ISSUE(c + 1, (c + 1) & 1);
        CP_COMMIT();

        const uint32_t bb = smem_base + (c & 1) * AVBUF;
        const uint32_t tEh = bb, tEl = bb + 16384;
        const uint32_t tVh = bb + 32768, tVl = bb + 40960;

#pragma unroll
        for (int ks = 0; ks < 4; ks++) {
            uint32_t ah[2][4], al[2][4];
#pragma unroll
            for (int mf = 0; mf < 2; mf++) {
                const uint32_t off = (uint32_t)((wm * 32 + mf * 16 + a_row) * 128
                                                + ks * 32 + a_c16);
                const uint32_t swo = SMEM_SWIZZLE_128B(off);
                ldsm4(ah[mf], tEh + swo);
                ldsm4(al[mf], tEl + swo);
            }
            uint32_t bh[8];
#pragma unroll
            for (int np = 0; np < 2; np++) {
                const uint32_t off = (uint32_t)((wn * 32 + np * 16 + b_row) * 128
                                                + ks * 32 + b_c16);
                ldsm4(&bh[np * 4], tVh + SMEM_SWIZZLE_128B(off));
            }
#pragma unroll
            for (int mf = 0; mf < 2; mf++)
#pragma unroll
                for (int nf = 0; nf < 4; nf++)
                    mma16816(acc[mf][nf], ah[mf], &bh[nf * 2]);
#pragma unroll
            for (int mf = 0; mf < 2; mf++)
#pragma unroll
                for (int nf = 0; nf < 4; nf++)
                    mma16816(acc[mf][nf], al[mf], &bh[nf * 2]);
            uint32_t bl[8];
#pragma unroll
            for (int np = 0; np < 2; np++) {
                const uint32_t off = (uint32_t)((wn * 32 + np * 16 + b_row) * 128
                                                + ks * 32 + b_c16);
                ldsm4(&bl[np * 4], tVl + SMEM_SWIZZLE_128B(off));
            }
#pragma unroll
            for (int mf = 0; mf < 2; mf++)
#pragma unroll
                for (int nf = 0; nf < 4; nf++)
                    mma16816(acc[mf][nf], ah[mf], &bl[nf * 2]);
        }
    }

    const int n = g >> 5, b = (g >> 3) & 3, hd = g & 7;
    const int gr = lane >> 2, c2 = (lane & 3) * 2;
#pragma unroll
    for (int mf = 0; mf < 2; mf++) {
#pragma unroll
        for (int nf = 0; nf < 4; nf++) {
            const int d = wn * 32 + nf * 8 + c2;
#pragma unroll
            for (int half = 0; half < 2; half++) {
                const int q = q0 + wm * 32 + mf * 16 + gr + half * 8;
                const size_t t = (size_t)(n * SEQ + q);
                const size_t off = t * EMBED + b * EBS + hd * HD + d;
                float h0, l0f, h1, l1;
                splitf(acc[mf][nf][half * 2 + 0], h0, l0f);
                splitf(acc[mf][nf][half * 2 + 1], h1, l1);
                *(uint32_t*)(g_AOh + off) = packbf2(h0, h1);
                *(uint32_t*)(g_AOl + off) = packbf2(l0f, l1);
            }
        }
    }
}

/* ------------------------------------------------------------------ */
extern "C" void kernel_launch(void* const* d_in, const int* in_sizes, int n_in,
                              void* d_out, int out_size)
{
    const float* values = (const float*)d_in[0];
    const float* keys   = (const float*)d_in[1];
    const float* query  = (const float*)d_in[2];
    const int*   mask   = (const int*)d_in[3];
    const float* Wv = (const float*)d_in[4];
    const float* bv = (const float*)d_in[5];
    const float* Wk = (const float*)d_in[6];
    const float* bk = (const float*)d_in[7];
    const float* Wq = (const float*)d_in[8];
    const float* bq = (const float*)d_in[9];
    const float* Wo = (const float*)d_in[10];
    const float* bo = (const float*)d_in[11];
    float* out = (float*)d_out;

    cudaFuncSetAttribute(mm_kernel<0>, cudaFuncAttributeMaxDynamicSharedMemorySize,
                         SMEM_GEMM_TOTAL);
    cudaFuncSetAttribute(mm_kernel<1>, cudaFuncAttributeMaxDynamicSharedMemorySize,
                         SMEM_GEMM_TOTAL);
    cudaFuncSetAttribute(energy_mma_kernel, cudaFuncAttributeMaxDynamicSharedMemorySize,
                         SMEM_ENERGY);
    cudaFuncSetAttribute(av_mma_kernel, cudaFuncAttributeMaxDynamicSharedMemorySize,
                         SMEM_AV);

    /* converts */
    dim3 gx((TTOK * EMBED) / (256 * 4), 3);
    convx_kernel<<<gx, 256>>>(values, keys, query);
    dim3 gw(EBS / 32, EBS / 32, 16);
    convw_kernel<<<gw, dim3(32, 8)>>>(Wv, Wk, Wq, Wo);
    convm_kernel<<<(NBATCH * SEQ) / 8, 256>>>(mask);

    /* fused qkv projections (tensor, 512 threads, 3-stage) */
    dim3 gqkv(EBS / 128, TTOK / 128, 12);
    mm_kernel<0><<<gqkv, 512, SMEM_GEMM_TOTAL>>>(bv, bk, bq, nullptr);

    /* energy + exp + column partial sums (tensor, 1 barrier/chunk) */
    dim3 ge(SEQ / 128, NG);
    energy_mma_kernel<<<ge, 256, SMEM_ENERGY>>>();

    /* reduce partials -> 1/Z, fold into V */
    zred_kernel<<<(NG * SEQ) / 256, 256>>>();
    vscale_kernel<<<(NG * HD * SEQ) / (256 * 8), 256>>>();

    /* AV (tensor, 1 barrier/chunk) */
    dim3 ga(SEQ / 128, NG);
    av_mma_kernel<<<ga, 256, SMEM_AV>>>();

    /* output projection (tensor, 512 threads, 3-stage) */
    dim3 go(EBS / 128, TTOK / 128, NB);
    mm_kernel<1><<<go, 512, SMEM_GEMM_TOTAL>>>(bo, nullptr, nullptr, out);
}

// round 17
// speedup vs baseline: 1.0356x; 1.0053x over previous
#include <cuda_runtime.h>
#include <cuda_bf16.h>
#include <math.h>
#include <stdint.h>

#define NBATCH 4
#define SEQ    1024
#define EMBED  2048
#define EBS    512
#define NB     4
#define HEADS  8
#define HD     64
#define TTOK   (NBATCH * SEQ)        /* 4096 tokens */
#define NG     (NBATCH * NB * HEADS) /* 128 (n,b,h) heads */

typedef unsigned long long u64;

#define SMEM_SWIZZLE_128B(off) ((off) ^ (((off) >> 3) & 0x70))

/* ================================================================== */
/* Tensor / async helpers (sm_80 path: legal on base sm_103 target)    */
/* ================================================================== */
__device__ __forceinline__ uint32_t smem_to_u32(const void* p) {
    uint32_t a;
    asm("{ .reg .u64 t; cvta.to.shared.u64 t, %1; cvt.u32.u64 %0, t; }"
        : "=r"(a) : "l"(p));
    return a;
}
__device__ __forceinline__ void ldsm4(uint32_t* r, uint32_t addr) {
    asm volatile("ldmatrix.sync.aligned.m8n8.x4.shared.b16 {%0,%1,%2,%3}, [%4];"
                 : "=r"(r[0]), "=r"(r[1]), "=r"(r[2]), "=r"(r[3]) : "r"(addr));
}
__device__ __forceinline__ void mma16816(float* d, const uint32_t* a,
                                         const uint32_t* b) {
    asm volatile(
        "mma.sync.aligned.m16n8k16.row.col.f32.bf16.bf16.f32 "
        "{%0,%1,%2,%3}, {%4,%5,%6,%7}, {%8,%9}, {%0,%1,%2,%3};"
        : "+f"(d[0]), "+f"(d[1]), "+f"(d[2]), "+f"(d[3])
        : "r"(a[0]), "r"(a[1]), "r"(a[2]), "r"(a[3]), "r"(b[0]), "r"(b[1]));
}
__device__ __forceinline__ void cpa16(uint32_t dst, const void* src) {
    asm volatile("cp.async.cg.shared.global [%0], [%1], 16;"
                 :: "r"(dst), "l"(src) : "memory");
}
#define CP_COMMIT() asm volatile("cp.async.commit_group;" ::: "memory")
#define CP_WAIT1()  asm volatile("cp.async.wait_group 1;" ::: "memory")
#define CP_WAIT0()  asm volatile("cp.async.wait_group 0;" ::: "memory")
__device__ __forceinline__ uint32_t packbf2(float a, float b) {
    __nv_bfloat162 p = __floats2bfloat162_rn(a, b);
    return *(uint32_t*)&p;
}
__device__ __forceinline__ void splitf(float v, float& hi, float& lo) {
    __nv_bfloat16 hb = __float2bfloat16_rn(v);
    hi = __bfloat162float(hb);
    lo = v - hi;
}
__device__ __forceinline__ float2 upk(uint32_t u) {
    __nv_bfloat162 b = *(__nv_bfloat162*)&u;
    return __bfloat1622float2(b);
}

/* ================================================================== */
/* Device scratch                                                      */
/* ================================================================== */
__device__ __align__(256) __nv_bfloat16 g_Eh[(size_t)NG * SEQ * SEQ]; /* 256 MB */
__device__ __align__(256) __nv_bfloat16 g_El[(size_t)NG * SEQ * SEQ]; /* 256 MB */
__device__ __align__(256) float g_Zp[16][NG * SEQ];
__device__ float g_Zi[NG * SEQ];
__device__ __align__(256) uint32_t g_Mb[NBATCH * SEQ * 32];           /* bit mask */
__device__ __align__(256) __nv_bfloat16 g_Xh[(size_t)3 * TTOK * EMBED];
__device__ __align__(256) __nv_bfloat16 g_Xl[(size_t)3 * TTOK * EMBED];
__device__ __align__(256) __nv_bfloat16 g_AOh[(size_t)TTOK * EMBED];
__device__ __align__(256) __nv_bfloat16 g_AOl[(size_t)TTOK * EMBED];
__device__ __align__(256) __nv_bfloat16 g_Wh[(size_t)4 * NB * EBS * EBS];
__device__ __align__(256) __nv_bfloat16 g_Wl[(size_t)4 * NB * EBS * EBS];
__device__ __align__(256) __nv_bfloat16 g_Qh[(size_t)NG * SEQ * HD];
__device__ __align__(256) __nv_bfloat16 g_Ql[(size_t)NG * SEQ * HD];
__device__ __align__(256) __nv_bfloat16 g_Kh[(size_t)NG * SEQ * HD];
__device__ __align__(256) __nv_bfloat16 g_Kl[(size_t)NG * SEQ * HD];
__device__ __align__(256) __nv_bfloat16 g_Vth[(size_t)NG * HD * SEQ]; /* [g][d][s] */
__device__ __align__(256) __nv_bfloat16 g_Vtl[(size_t)NG * HD * SEQ];

/* ================================================================== */
/* Converters                                                          */
/* ================================================================== */
__global__ __launch_bounds__(256) void convx_kernel(
    const float* __restrict__ V, const float* __restrict__ K,
    const float* __restrict__ Q)
{
    const int p = blockIdx.y;
    const float* src = (p == 0) ? V : (p == 1) ? K : Q;
    __nv_bfloat16* dh = g_Xh + (size_t)p * TTOK * EMBED;
    __nv_bfloat16* dl = g_Xl + (size_t)p * TTOK * EMBED;
    const size_t i = ((size_t)blockIdx.x * 256 + threadIdx.x) * 4;
    float4 v = *(const float4*)(src + i);
    float f[4] = {v.x, v.y, v.z, v.w};
    float hi[4], lo[4];
#pragma unroll
    for (int j = 0; j < 4; j++) splitf(f[j], hi[j], lo[j]);
    uint2 hv, lv;
    hv.x = packbf2(hi[0], hi[1]); hv.y = packbf2(hi[2], hi[3]);
    lv.x = packbf2(lo[0], lo[1]); lv.y = packbf2(lo[2], lo[3]);
    *(uint2*)(dh + i) = hv;
    *(uint2*)(dl + i) = lv;
}

__global__ __launch_bounds__(256) void convw_kernel(
    const float* __restrict__ Wv, const float* __restrict__ Wk,
    const float* __restrict__ Wq, const float* __restrict__ Wo)
{
    __shared__ float st[32][33];
    const int z = blockIdx.z;
    const int wi = z >> 2, b = z & 3;
    const float* W = ((wi == 0) ? Wv : (wi == 1) ? Wk : (wi == 2) ? Wq : Wo)
                     + (size_t)b * EBS * EBS;
    const int i0 = blockIdx.y * 32, o0 = blockIdx.x * 32;
    const int tx = threadIdx.x, ty = threadIdx.y;
#pragma unroll
    for (int kk = 0; kk < 4; kk++)
        st[ty + 8 * kk][tx] = W[(size_t)(i0 + ty + 8 * kk) * EBS + o0 + tx];
    __syncthreads();
    __nv_bfloat16* oh = g_Wh + (size_t)(wi * NB + b) * EBS * EBS;
    __nv_bfloat16* ol = g_Wl + (size_t)(wi * NB + b) * EBS * EBS;
#pragma unroll
    for (int kk = 0; kk < 4; kk++) {
        const float v = st[tx][ty + 8 * kk];
        float h, l;
        splitf(v, h, l);
        const size_t off = (size_t)(o0 + ty + 8 * kk) * EBS + i0 + tx;
        oh[off] = __float2bfloat16_rn(h);
        ol[off] = __float2bfloat16_rn(l);
    }
}

/* pack mask int32 -> bits */
__global__ __launch_bounds__(256) void convm_kernel(const int* __restrict__ mask)
{
    const int wid = threadIdx.x >> 5, lane = threadIdx.x & 31;
    const int r = blockIdx.x * 8 + wid;
    const int* row = mask + (size_t)r * SEQ;
    uint32_t* orow = g_Mb + (size_t)r * 32;
    for (int w = 0; w < 32; w++) {
        const int m = row[w * 32 + lane];
        const uint32_t bits = __ballot_sync(0xffffffffu, m != 0);
        if (lane == 0) orow[w] = bits;
    }
}

/* ================================================================== */
/* mma.sync bf16 3-split projection GEMM (R13 config).                 */
/* 512 threads (16 warps as 4m x 4n, warp tile 32x32), 128x128 CTA     */
/* tile, K=512 in 8 chunks of 64, 3-stage cp.async ring, single        */
/* __syncthreads per chunk. V epilogue coalesced (SS=130).             */
/* ================================================================== */
#define KCHUNK 64
#define NCHUNKS 8
#define TILE_BYTES 16384
#define MMBUF (4 * TILE_BYTES)            /* 64 KB per chunk buffer */
#define SS 130
#define SMEM_GEMM_TOTAL (3 * MMBUF)       /* 192 KB */

template <int MODE>
__global__ __launch_bounds__(512) void mm_kernel(
    const float* __restrict__ bias0, const float* __restrict__ bias1,
    const float* __restrict__ bias2, float* __restrict__ oout)
{
    extern __shared__ char smem[];
    const uint32_t smem_base = smem_to_u32(smem);
    const int tid = threadIdx.x;
    const int wid = tid >> 5, lane = tid & 31;
    const int wm = wid & 3, wn = wid >> 2;   /* 4x4 warp grid, 32x32 tiles */

    int p, b;
    const __nv_bfloat16 *Ah, *Al;
    const float* bias;
    if (MODE == 0) {
        p = blockIdx.z >> 2; b = blockIdx.z & 3;
        Ah = g_Xh + (size_t)p * TTOK * EMBED;
        Al = g_Xl + (size_t)p * TTOK * EMBED;
        bias = (p == 0) ? bias0 : (p == 1) ? bias1 : bias2;
    } else {
        p = 3; b = blockIdx.z;
        Ah = g_AOh; Al = g_AOl;
        bias = bias0;
    }
    const __nv_bfloat16* Bh = g_Wh + (size_t)(p * NB + b) * EBS * EBS;
    const __nv_bfloat16* Bl = g_Wl + (size_t)(p * NB + b) * EBS * EBS;
    const int m0 = blockIdx.y * 128, n0 = blockIdx.x * 128;

    /* loaders: 512 threads, each 32B per 16KB tile (2 x cpa16) */
    const int lrow = tid >> 2;
    const int lseg = (tid & 3) * 16;          /* bf16 elems */
    const __nv_bfloat16* Arow_h = Ah + (size_t)(m0 + lrow) * EMBED + b * EBS + lseg;
    const __nv_bfloat16* Arow_l = Al + (size_t)(m0 + lrow) * EMBED + b * EBS + lseg;
    const __nv_bfloat16* Brow_h = Bh + (size_t)(n0 + lrow) * EBS + lseg;
    const __nv_bfloat16* Brow_l = Bl + (size_t)(n0 + lrow) * EBS + lseg;
    uint32_t sw[2];
#pragma unroll
    for (int j = 0; j < 2; j++)
        sw[j] = SMEM_SWIZZLE_128B((uint32_t)(lrow * 128 + (lseg + j * 8) * 2));

#define MM_ISSUE(cc, buf)                                                      \
    do {                                                                       \
        const int _co = (cc) * KCHUNK;                                         \
        const uint32_t _bb = smem_base + (buf) * MMBUF;                        \
        _Pragma("unroll")                                                      \
        for (int j = 0; j < 2; j++) {                                          \
            cpa16(_bb + 0 * TILE_BYTES + sw[j], Arow_h + _co + j * 8);         \
            cpa16(_bb + 1 * TILE_BYTES + sw[j], Arow_l + _co + j * 8);         \
            cpa16(_bb + 2 * TILE_BYTES + sw[j], Brow_h + _co + j * 8);         \
            cpa16(_bb + 3 * TILE_BYTES + sw[j], Brow_l + _co + j * 8);         \
        }                                                                      \
    } while (0)

    MM_ISSUE(0, 0);
    CP_COMMIT();
    MM_ISSUE(1, 1);
    CP_COMMIT();

    const int a_row = (lane & 15);
    const int a_c16 = (lane >> 4) * 16;
    const int b_row = (lane & 7) + ((lane >> 4) << 3);
    const int b_c16 = ((lane >> 3) & 1) * 16;

    float acc[2][4][4];
#pragma unroll
    for (int mf = 0; mf < 2; mf++)
#pragma unroll
        for (int nf = 0; nf < 4; nf++)
#pragma unroll
            for (int r = 0; r < 4; r++) acc[mf][nf][r] = 0.f;

    int rbuf = 0;
    for (int c = 0; c < NCHUNKS; c++) {
        CP_WAIT1();
        __syncthreads();
        if (c + 2 < NCHUNKS) {
            const int ibuf = (rbuf + 2 >= 3) ? rbuf + 2 - 3 : rbuf + 2;
            MM_ISSUE(c + 2, ibuf);
        }
        CP_COMMIT();

        const uint32_t bb = smem_base + rbuf * MMBUF;
        const uint32_t tAh = bb, tAl = bb + TILE_BYTES;
        const uint32_t tBh = bb + 2 * TILE_BYTES, tBl = bb + 3 * TILE_BYTES;

#pragma unroll
        for (int ks = 0; ks < 4; ks++) {
            uint32_t ah[2][4], al[2][4];
#pragma unroll
            for (int mf = 0; mf < 2; mf++) {
                const uint32_t off = (uint32_t)((wm * 32 + mf * 16 + a_row) * 128
                                                + ks * 32 + a_c16);
                const uint32_t swo = SMEM_SWIZZLE_128B(off);
                ldsm4(ah[mf], tAh + swo);
                ldsm4(al[mf], tAl + swo);
            }
            uint32_t bh[8];
#pragma unroll
            for (int np = 0; np < 2; np++) {
                const uint32_t off = (uint32_t)((wn * 32 + np * 16 + b_row) * 128
                                                + ks * 32 + b_c16);
                ldsm4(&bh[np * 4], tBh + SMEM_SWIZZLE_128B(off));
            }
#pragma unroll
            for (int mf = 0; mf < 2; mf++)
#pragma unroll
                for (int nf = 0; nf < 4; nf++)
                    mma16816(acc[mf][nf], ah[mf], &bh[nf * 2]);
#pragma unroll
            for (int mf = 0; mf < 2; mf++)
#pragma unroll
                for (int nf = 0; nf < 4; nf++)
                    mma16816(acc[mf][nf], al[mf], &bh[nf * 2]);
            uint32_t bl[8];
#pragma unroll
            for (int np = 0; np < 2; np++) {
                const uint32_t off = (uint32_t)((wn * 32 + np * 16 + b_row) * 128
                                                + ks * 32 + b_c16);
                ldsm4(&bl[np * 4], tBl + SMEM_SWIZZLE_128B(off));
            }
#pragma unroll
            for (int mf = 0; mf < 2; mf++)
#pragma unroll
                for (int nf = 0; nf < 4; nf++)
                    mma16816(acc[mf][nf], ah[mf], &bl[nf * 2]);
        }
        rbuf = (rbuf + 1 >= 3) ? 0 : rbuf + 1;
    }
    CP_WAIT0();
    __syncthreads();

    float* stg = (float*)smem;  /* [128][SS] */
    const int gr = lane >> 2, c2 = (lane & 3) * 2;
#pragma unroll
    for (int mf = 0; mf < 2; mf++) {
        const int row0 = wm * 32 + mf * 16 + gr;
#pragma unroll
        for (int nf = 0; nf < 4; nf++) {
            const int col = wn * 32 + nf * 8 + c2;
            *(float2*)&stg[row0 * SS + col]       = make_float2(acc[mf][nf][0], acc[mf][nf][1]);
            *(float2*)&stg[(row0 + 8) * SS + col] = make_float2(acc[mf][nf][2], acc[mf][nf][3]);
        }
    }
    __syncthreads();

    if (MODE == 0) {
        const int n = m0 >> 10, s0 = m0 & (SEQ - 1);
        const int h0 = n0 >> 6;
        if (p >= 1) {
            __nv_bfloat16* oh = (p == 1) ? g_Kh : g_Qh;
            __nv_bfloat16* ol = (p == 1) ? g_Kl : g_Ql;
#pragma unroll
            for (int it = 0; it < 8; it++) {
                const int flat = tid + it * 512;
                const int srow = flat >> 5;
                const int rem = flat & 31;
                const int hh = rem >> 4, dq = (rem & 15) * 4;
                const int ocol = hh * 64 + dq;
                float hi[4], lo[4];
#pragma unroll
                for (int j = 0; j < 4; j++) {
                    const float v = stg[srow * SS + ocol + j]
                                    + bias[b * EBS + n0 + ocol + j];
                    splitf(v, hi[j], lo[j]);
                }
                uint2 hv, lv;
                hv.x = packbf2(hi[0], hi[1]); hv.y = packbf2(hi[2], hi[3]);
                lv.x = packbf2(lo[0], lo[1]); lv.y = packbf2(lo[2], lo[3]);
                const size_t gidx = (size_t)((n * NB + b) * HEADS + h0 + hh);
                const size_t off = (gidx * SEQ + s0 + srow) * HD + dq;
                *(uint2*)(oh + off) = hv;
                *(uint2*)(ol + off) = lv;
            }
        } else {
            /* V: bf16 hi/lo transposed [g][d][s] — coalesced stores:
               flat = (dcol, s-chunk of 8); 16 consecutive lanes cover one
               contiguous 256B row segment. */
#pragma unroll
            for (int it = 0; it < 4; it++) {
                const int flat = tid + it * 512;     /* 0..2047 */
                const int dcol = flat >> 4;          /* 0..127  */
                const int sc   = (flat & 15) * 8;    /* 0..120  */
                const int hh = dcol >> 6, dl = dcol & 63;
                const size_t gidx = (size_t)((n * NB + b) * HEADS + h0 + hh);
                const float bb = bias[b * EBS + n0 + dcol];
                float hi[8], lo[8];
#pragma unroll
                for (int j = 0; j < 8; j++) {
                    const float v = stg[(sc + j) * SS + dcol] + bb;
                    splitf(v, hi[j], lo[j]);
                }
                uint4 hv, lv;
                hv.x = packbf2(hi[0], hi[1]); hv.y = packbf2(hi[2], hi[3]);
                hv.z = packbf2(hi[4], hi[5]); hv.w = packbf2(hi[6], hi[7]);
                lv.x = packbf2(lo[0], lo[1]); lv.y = packbf2(lo[2], lo[3]);
                lv.z = packbf2(lo[4], lo[5]); lv.w = packbf2(lo[6], lo[7]);
                const size_t off = (gidx * HD + dl) * SEQ + s0 + sc;
                *(uint4*)(g_Vth + off) = hv;
                *(uint4*)(g_Vtl + off) = lv;
            }
        }
    } else {
#pragma unroll
        for (int it = 0; it < 8; it++) {
            const int flat = tid + it * 512;
            const int srow = flat >> 5;
            const int oq = (flat & 31) * 4;
            float4 v;
            v.x = stg[srow * SS + oq + 0] + bias[b * EBS + n0 + oq + 0];
            v.y = stg[srow * SS + oq + 1] + bias[b * EBS + n0 + oq + 1];
            v.z = stg[srow * SS + oq + 2] + bias[b * EBS + n0 + oq + 2];
            v.w = stg[srow * SS + oq + 3] + bias[b * EBS + n0 + oq + 3];
            *(float4*)(oout + (size_t)(m0 + srow) * EMBED + b * EBS + n0 + oq) = v;
        }
    }
}

/* ================================================================== */
/* Energy v2 (R13): Q resident, K cp.async streamed, wait1 depth-2.    */
/* ================================================================== */
#define TILE16K 16384
#define SMEM_ENERGY 98304

__global__ __launch_bounds__(256, 2) void energy_mma_kernel()
{
    extern __shared__ char smem[];
    const uint32_t smem_base = smem_to_u32(smem);
    const int tid = threadIdx.x;
    const int wid = tid >> 5, lane = tid & 31;
    const int wm = wid & 1, wn = wid >> 1;

    const int g  = blockIdx.y;
    const int qt = blockIdx.x;
    const int q0 = qt * 128;
    const int n = g >> 5;

    const uint32_t tQh = smem_base;
    const uint32_t tQl = smem_base + TILE16K;

    const int lrow = tid >> 1;
    const int lhalf = (tid & 1) * 32;
    uint32_t sw[4];
#pragma unroll
    for (int gix = 0; gix < 4; gix++)
        sw[gix] = SMEM_SWIZZLE_128B((uint32_t)(lrow * 128 + (lhalf + gix * 8) * 2));

    const __nv_bfloat16* qh = g_Qh + ((size_t)g * SEQ + q0 + lrow) * HD + lhalf;
    const __nv_bfloat16* ql = g_Ql + ((size_t)g * SEQ + q0 + lrow) * HD + lhalf;
    const __nv_bfloat16* khb = g_Kh + ((size_t)g * SEQ + lrow) * HD + lhalf;
    const __nv_bfloat16* klb = g_Kl + ((size_t)g * SEQ + lrow) * HD + lhalf;

#pragma unroll
    for (int gix = 0; gix < 4; gix++) {
        cpa16(tQh + sw[gix], qh + gix * 8);
        cpa16(tQl + sw[gix], ql + gix * 8);
    }
    {
        const uint32_t kb = smem_base + 2 * TILE16K;
#pragma unroll
        for (int gix = 0; gix < 4; gix++) {
            cpa16(kb + sw[gix], khb + gix * 8);
            cpa16(kb + TILE16K + sw[gix], klb + gix * 8);
        }
    }
    CP_COMMIT();
    {
        const uint32_t kb = smem_base + 4 * TILE16K;
        const size_t so = (size_t)128 * HD;
#pragma unroll
        for (int gix = 0; gix < 4; gix++) {
            cpa16(kb + sw[gix], khb + so + gix * 8);
            cpa16(kb + TILE16K + sw[gix], klb + so + gix * 8);
        }
    }
    CP_COMMIT();

    const int a_row = (lane & 15);
    const int a_c16 = (lane >> 4) * 16;
    const int b_row = (lane & 7) + ((lane >> 4) << 3);
    const int b_c16 = ((lane >> 3) & 1) * 16;
    const int gr = lane >> 2, c2 = (lane & 3) * 2;

    const uint32_t* Mbn = g_Mb + (size_t)n * SEQ * 32;
    __nv_bfloat16* Egh = g_Eh + (size_t)g * SEQ * SEQ;
    __nv_bfloat16* Egl = g_El + (size_t)g * SEQ * SEQ;

    for (int c = 0; c < 8; c++) {
        CP_WAIT1();
        __syncthreads();
        const uint32_t tKh = smem_base + (2 + 2 * (c & 1)) * TILE16K;
        const uint32_t tKl = tKh + TILE16K;

        float acc[4][4][4];
#pragma unroll
        for (int mf = 0; mf < 4; mf++)
#pragma unroll
            for (int nf = 0; nf < 4; nf++)
#pragma unroll
                for (int r = 0; r < 4; r++) acc[mf][nf][r] = 0.f;

#pragma unroll
        for (int ks = 0; ks < 4; ks++) {
            uint32_t ah[4][4], al[4][4];
#pragma unroll
            for (int mf = 0; mf < 4; mf++) {
                const uint32_t off = (uint32_t)((wm * 64 + mf * 16 + a_row) * 128
                                                + ks * 32 + a_c16);
                const uint32_t swo = SMEM_SWIZZLE_128B(off);
                ldsm4(ah[mf], tQh + swo);
                ldsm4(al[mf], tQl + swo);
            }
            uint32_t bh[8];
#pragma unroll
            for (int np = 0; np < 2; np++) {
                const uint32_t off = (uint32_t)((wn * 32 + np * 16 + b_row) * 128
                                                + ks * 32 + b_c16);
                ldsm4(&bh[np * 4], tKh + SMEM_SWIZZLE_128B(off));
            }
#pragma unroll
            for (int mf = 0; mf < 4; mf++)
#pragma unroll
                for (int nf = 0; nf < 4; nf++)
                    mma16816(acc[mf][nf], ah[mf], &bh[nf * 2]);
#pragma unroll
            for (int mf = 0; mf < 4; mf++)
#pragma unroll
                for (int nf = 0; nf < 4; nf++)
                    mma16816(acc[mf][nf], al[mf], &bh[nf * 2]);
            uint32_t bl[8];
#pragma unroll
            for (int np = 0; np < 2; np++) {
                const uint32_t off = (uint32_t)((wn * 32 + np * 16 + b_row) * 128
                                                + ks * 32 + b_c16);
                ldsm4(&bl[np * 4], tKl + SMEM_SWIZZLE_128B(off));
            }
#pragma unroll
            for (int mf = 0; mf < 4; mf++)
#pragma unroll
                for (int nf = 0; nf < 4; nf++)
                    mma16816(acc[mf][nf], ah[mf], &bl[nf * 2]);
        }
        __syncthreads();

        if (c + 2 < 8) {
            const uint32_t kb = smem_base + (2 + 2 * (c & 1)) * TILE16K;
            const size_t so = (size_t)(c + 2) * 128 * HD;
#pragma unroll
            for (int gix = 0; gix < 4; gix++) {
                cpa16(kb + sw[gix], khb + so + gix * 8);
                cpa16(kb + TILE16K + sw[gix], klb + so + gix * 8);
            }
        }
        CP_COMMIT();

        const int l0 = c * 128;
        const int cw = c * 4 + wn;
        float csum[4][2];
#pragma unroll
        for (int nf = 0; nf < 4; nf++) { csum[nf][0] = 0.f; csum[nf][1] = 0.f; }

#pragma unroll
        for (int mf = 0; mf < 4; mf++) {
#pragma unroll
            for (int half = 0; half < 2; half++) {
                const int q = q0 + wm * 64 + mf * 16 + gr + half * 8;
                const uint32_t w = Mbn[q * 32 + cw];
#pragma unroll
                for (int nf = 0; nf < 4; nf++) {
                    const int col = l0 + wn * 32 + nf * 8 + c2;
                    const uint32_t bits = (w >> (nf * 8 + c2)) & 3u;
                    float2 e;
                    e.x = (bits & 1u) ? __expf(acc[mf][nf][half * 2 + 0] * 0.125f) : 0.f;
                    e.y = (bits & 2u) ? __expf(acc[mf][nf][half * 2 + 1] * 0.125f) : 0.f;
                    float h0, lo0, h1, lo1;
                    splitf(e.x, h0, lo0);
                    splitf(e.y, h1, lo1);
                    *(uint32_t*)(Egh + (size_t)q * SEQ + col) = packbf2(h0, h1);
                    *(uint32_t*)(Egl + (size_t)q * SEQ + col) = packbf2(lo0, lo1);
                    csum[nf][0] += e.x;
                    csum[nf][1] += e.y;
                }
            }
        }
        float* Zp = g_Zp[qt * 2 + wm] + g * SEQ;
#pragma unroll
        for (int nf = 0; nf < 4; nf++) {
#pragma unroll
            for (int cc = 0; cc < 2; cc++) {
                float v = csum[nf][cc];
                v += __shfl_xor_sync(0xffffffffu, v, 4);
                v += __shfl_xor_sync(0xffffffffu, v, 8);
                v += __shfl_xor_sync(0xffffffffu, v, 16);
                if (gr == 0)
                    Zp[l0 + wn * 32 + nf * 8 + c2 + cc] = v;
            }
        }
    }
}

/* ================================================================== */
__global__ __launch_bounds__(256) void zred_kernel()
{
    const int i = blockIdx.x * 256 + threadIdx.x;
    float z = 0.f;
#pragma unroll
    for (int s = 0; s < 16; s++)
        z += g_Zp[s][i];
    g_Zi[i] = (z > 0.f) ? (1.f / z) : 0.f;
}

/* ================================================================== */
__global__ __launch_bounds__(256) void vscale_kernel()
{
    const size_t e = ((size_t)blockIdx.x * 256 + threadIdx.x) * 8;
    const int g = (int)(e / ((size_t)HD * SEQ));
    const int s = (int)(e % SEQ);
    float4 z0 = *(const float4*)(g_Zi + g * SEQ + s);
    float4 z1 = *(const float4*)(g_Zi + g * SEQ + s + 4);
    const float zz[8] = {z0.x, z0.y, z0.z, z0.w, z1.x, z1.y, z1.z, z1.w};
    uint4 vh = *(const uint4*)(g_Vth + e);
    uint4 vl = *(const uint4*)(g_Vtl + e);
    const uint32_t hw[4] = {vh.x, vh.y, vh.z, vh.w};
    const uint32_t lw[4] = {vl.x, vl.y, vl.z, vl.w};
    uint32_t oh[4], ol[4];
#pragma unroll
    for (int j = 0; j < 4; j++) {
        float2 fh = upk(hw[j]);
        float2 fl = upk(lw[j]);
        const float a = (fh.x + fl.x) * zz[2 * j];
        const float b = (fh.y + fl.y) * zz[2 * j + 1];
        float ah, alo, bh, blo;
        splitf(a, ah, alo);
        splitf(b, bh, blo);
        oh[j] = packbf2(ah, bh);
        ol[j] = packbf2(alo, blo);
    }
    *(uint4*)(g_Vth + e) = make_uint4(oh[0], oh[1], oh[2], oh[3]);
    *(uint4*)(g_Vtl + e) = make_uint4(ol[0], ol[1], ol[2], ol[3]);
}

/* ================================================================== */
/* AV v2 (R13): pure GEMM, cp.async double-buffered (wait1, depth 2).  */
/* ================================================================== */
#define AVBUF 49152
#define SMEM_AV (2 * AVBUF)

__global__ __launch_bounds__(256, 2) void av_mma_kernel()
{
    extern __shared__ char smem[];
    const uint32_t smem_base = smem_to_u32(smem);
    const int tid = threadIdx.x;
    const int wid = tid >> 5, lane = tid & 31;
    const int wm = wid >> 1, wn = wid & 1;

    const int g  = blockIdx.y;
    const int q0 = blockIdx.x * 128;

    const int erow = tid >> 1;
    const int ebyte = (tid & 1) * 64;
    const __nv_bfloat16* ehb = g_Eh + ((size_t)g * SEQ + q0 + erow) * SEQ + ebyte / 2;
    const __nv_bfloat16* elb = g_El + ((size_t)g * SEQ + q0 + erow) * SEQ + ebyte / 2;
    uint32_t esw[4];
#pragma unroll
    for (int gix = 0; gix < 4; gix++)
        esw[gix] = SMEM_SWIZZLE_128B((uint32_t)(erow * 128 + ebyte + gix * 16));

    const int vrow = tid >> 2;
    const int vbyte = (tid & 3) * 32;
    const __nv_bfloat16* vhb = g_Vth + ((size_t)g * HD + vrow) * SEQ + vbyte / 2;
    const __nv_bfloat16* vlb = g_Vtl + ((size_t)g * HD + vrow) * SEQ + vbyte / 2;
    uint32_t vsw[2];
#pragma unroll
    for (int j = 0; j < 2; j++)
        vsw[j] = SMEM_SWIZZLE_128B((uint32_t)(vrow * 128 + vbyte + j * 16));

#define AV_ISSUE(cc, buf)                                                      \
    do {                                                                       \
        const int _l0 = (cc) * 64;                                             \
        const uint32_t _bb = smem_base + (buf) * AVBUF;                        \
        _Pragma("unroll")                                                      \
        for (int gix = 0; gix < 4; gix++) {                                    \
            cpa16(_bb + esw[gix], ehb + _l0 + gix * 8);                        \
            cpa16(_bb + 16384 + esw[gix], elb + _l0 + gix * 8);                \
        }                                                                      \
        _Pragma("unroll")                                                      \
        for (int j = 0; j < 2; j++) {                                          \
            cpa16(_bb + 32768 + vsw[j], vhb + _l0 + j * 8);                    \
            cpa16(_bb + 40960 + vsw[j], vlb + _l0 + j * 8);                    \
        }                                                                      \
    } while (0)

    AV_ISSUE(0, 0);
    CP_COMMIT();
    AV_ISSUE(1, 1);
    CP_COMMIT();

    const int a_row = (lane & 15);
    const int a_c16 = (lane >> 4) * 16;
    const int b_row = (lane & 7) + ((lane >> 4) << 3);
    const int b_c16 = ((lane >> 3) & 1) * 16;

    float acc[2][4][4];
#pragma unroll
    for (int mf = 0; mf < 2; mf++)
#pragma unroll
        for (int nf = 0; nf < 4; nf++)
#pragma unroll
            for (int r = 0; r < 4; r++) acc[mf][nf][r] = 0.f;

    for (int c = 0; c < 16; c++) {
        CP_WAIT1();
        __syncthreads();
        const uint32_t bb = smem_base + (c & 1) * AVBUF;
        const uint32_t tEh = bb, tEl = bb + 16384;
        const uint32_t tVh = bb + 32768, tVl = bb + 40960;

#pragma unroll
        for (int ks = 0; ks < 4; ks++) {
            uint32_t ah[2][4], al[2][4];
#pragma unroll
            for (int mf = 0; mf < 2; mf++) {
                const uint32_t off = (uint32_t)((wm * 32 + mf * 16 + a_row) * 128
                                                + ks * 32 + a_c16);
                const uint32_t swo = SMEM_SWIZZLE_128B(off);
                ldsm4(ah[mf], tEh + swo);
                ldsm4(al[mf], tEl + swo);
            }
            uint32_t bh[8];
#pragma unroll
            for (int np = 0; np < 2; np++) {
                const uint32_t off = (uint32_t)((wn * 32 + np * 16 + b_row) * 128
                                                + ks * 32 + b_c16);
                ldsm4(&bh[np * 4], tVh + SMEM_SWIZZLE_128B(off));
            }
#pragma unroll
            for (int mf = 0; mf < 2; mf++)
#pragma unroll
                for (int nf = 0; nf < 4; nf++)
                    mma16816(acc[mf][nf], ah[mf], &bh[nf * 2]);
#pragma unroll
            for (int mf = 0; mf < 2; mf++)
#pragma unroll
                for (int nf = 0; nf < 4; nf++)
                    mma16816(acc[mf][nf], al[mf], &bh[nf * 2]);
            uint32_t bl[8];
#pragma unroll
            for (int np = 0; np < 2; np++) {
                const uint32_t off = (uint32_t)((wn * 32 + np * 16 + b_row) * 128
                                                + ks * 32 + b_c16);
                ldsm4(&bl[np * 4], tVl + SMEM_SWIZZLE_128B(off));
            }
#pragma unroll
            for (int mf = 0; mf < 2; mf++)
#pragma unroll
                for (int nf = 0; nf < 4; nf++)
                    mma16816(acc[mf][nf], ah[mf], &bl[nf * 2]);
        }
        __syncthreads();
        if (c + 2 < 16)
            AV_ISSUE(c + 2, c & 1);
        CP_COMMIT();
    }

    const int n = g >> 5, b = (g >> 3) & 3, hd = g & 7;
    const int gr = lane >> 2, c2 = (lane & 3) * 2;
#pragma unroll
    for (int mf = 0; mf < 2; mf++) {
#pragma unroll
        for (int nf = 0; nf < 4; nf++) {
            const int d = wn * 32 + nf * 8 + c2;
#pragma unroll
            for (int half = 0; half < 2; half++) {
                const int q = q0 + wm * 32 + mf * 16 + gr + half * 8;
                const size_t t = (size_t)(n * SEQ + q);
                const size_t off = t * EMBED + b * EBS + hd * HD + d;
                float h0, l0f, h1, l1;
                splitf(acc[mf][nf][half * 2 + 0], h0, l0f);
                splitf(acc[mf][nf][half * 2 + 1], h1, l1);
                *(uint32_t*)(g_AOh + off) = packbf2(h0, h1);
                *(uint32_t*)(g_AOl + off) = packbf2(l0f, l1);
            }
        }
    }
}

/* ------------------------------------------------------------------ */
extern "C" void kernel_launch(void* const* d_in, const int* in_sizes, int n_in,
                              void* d_out, int out_size)
{
    const float* values = (const float*)d_in[0];
    const float* keys   = (const float*)d_in[1];
    const float* query  = (const float*)d_in[2];
    const int*   mask   = (const int*)d_in[3];
    const float* Wv = (const float*)d_in[4];
    const float* bv = (const float*)d_in[5];
    const float* Wk = (const float*)d_in[6];
    const float* bk = (const float*)d_in[7];
    const float* Wq = (const float*)d_in[8];
    const float* bq = (const float*)d_in[9];
    const float* Wo = (const float*)d_in[10];
    const float* bo = (const float*)d_in[11];
    float* out = (float*)d_out;

    cudaFuncSetAttribute(mm_kernel<0>, cudaFuncAttributeMaxDynamicSharedMemorySize,
                         SMEM_GEMM_TOTAL);
    cudaFuncSetAttribute(mm_kernel<1>, cudaFuncAttributeMaxDynamicSharedMemorySize,
                         SMEM_GEMM_TOTAL);
    cudaFuncSetAttribute(energy_mma_kernel, cudaFuncAttributeMaxDynamicSharedMemorySize,
                         SMEM_ENERGY);
    cudaFuncSetAttribute(av_mma_kernel, cudaFuncAttributeMaxDynamicSharedMemorySize,
                         SMEM_AV);

    /* converts */
    dim3 gx((TTOK * EMBED) / (256 * 4), 3);
    convx_kernel<<<gx, 256>>>(values, keys, query);
    dim3 gw(EBS / 32, EBS / 32, 16);
    convw_kernel<<<gw, dim3(32, 8)>>>(Wv, Wk, Wq, Wo);
    convm_kernel<<<(NBATCH * SEQ) / 8, 256>>>(mask);

    /* fused qkv projections (tensor, 512 threads, 3-stage) */
    dim3 gqkv(EBS / 128, TTOK / 128, 12);
    mm_kernel<0><<<gqkv, 512, SMEM_GEMM_TOTAL>>>(bv, bk, bq, nullptr);

    /* energy + exp + column partial sums (tensor, pipelined) */
    dim3 ge(SEQ / 128, NG);
    energy_mma_kernel<<<ge, 256, SMEM_ENERGY>>>();

    /* reduce partials -> 1/Z, fold into V */
    zred_kernel<<<(NG * SEQ) / 256, 256>>>();
    vscale_kernel<<<(NG * HD * SEQ) / (256 * 8), 256>>>();

    /* AV (tensor, pipelined) */
    dim3 ga(SEQ / 128, NG);
    av_mma_kernel<<<ga, 256, SMEM_AV>>>();

    /* output projection (tensor, 512 threads, 3-stage) */
    dim3 go(EBS / 128, TTOK / 128, NB);
    mm_kernel<1><<<go, 512, SMEM_GEMM_TOTAL>>>(bo, nullptr, nullptr, out);
}